// round 1
// baseline (speedup 1.0000x reference)
#include <cuda_runtime.h>
#include <math.h>
#include <stdint.h>

// ---------------- problem constants (fixed shapes) ----------------
#define Bsz   4
#define Ntok  16384
#define Dm    256
#define LDm   64
#define Hm    128
#define Wm    128
#define HWm   (Hm*Wm)
#define Hsrc  512
#define Wsrc  512
#define CATD  320
#define HIDD  1024

// ---------------- scratch (static device globals; no allocs) ------
__device__ float g_loc_extra[Bsz*Ntok*2];
__device__ float g_acc [Bsz*HWm*257];                 // scatter accumulator (feat..., count)
__device__ float g_feat[Bsz*HWm*257];                 // normalized feature + mask channel
__device__ float g_fmap[(size_t)Bsz*HWm*256];         // reconstructed map, (b,y,x,c)
__device__ float g_cat [(size_t)Bsz*Ntok*CATD];       // [extra_inter(256) | extra_ln2(64)]
__device__ float g_hid [(size_t)Bsz*Ntok*HIDD];       // fc1 output

// ---------------- K0: zero the scatter accumulator ----------------
__global__ void k_zero_acc() {
    size_t n4 = (size_t)Bsz*HWm*257/4;
    size_t i = (size_t)blockIdx.x*blockDim.x + threadIdx.x;
    if (i < n4) ((float4*)g_acc)[i] = make_float4(0.f,0.f,0.f,0.f);
}

// ---------------- K1: LN1 + delta + loc_extra + loc outputs -------
__global__ void k_delta(const float* __restrict__ x, const float* __restrict__ loc,
                        const float* __restrict__ wd, const float* __restrict__ bd,
                        const float* __restrict__ n1g, const float* __restrict__ n1b,
                        float* __restrict__ out_loc_base)
{
    int w = (blockIdx.x*blockDim.x + threadIdx.x) >> 5;
    int lane = threadIdx.x & 31;
    if (w >= Bsz*Ntok) return;
    const float* xr = x + (size_t)w*Dm;
    float v[8], s = 0.f, sq = 0.f;
#pragma unroll
    for (int k = 0; k < 8; k++) { v[k] = xr[lane + 32*k]; s += v[k]; sq += v[k]*v[k]; }
#pragma unroll
    for (int o = 16; o > 0; o >>= 1) { s += __shfl_xor_sync(0xffffffffu, s, o); sq += __shfl_xor_sync(0xffffffffu, sq, o); }
    float m   = s  * (1.f/256.f);
    float var = sq * (1.f/256.f) - m*m;
    float r   = rsqrtf(var + 1e-5f);
    float d0 = 0.f, d1 = 0.f;
#pragma unroll
    for (int k = 0; k < 8; k++) {
        int c = lane + 32*k;
        float y = (v[k]-m)*r*n1g[c] + n1b[c];
        d0 += y * wd[2*c];
        d1 += y * wd[2*c+1];
    }
#pragma unroll
    for (int o = 16; o > 0; o >>= 1) { d0 += __shfl_xor_sync(0xffffffffu, d0, o); d1 += __shfl_xor_sync(0xffffffffu, d1, o); }
    if (lane == 0) {
        float l0 = loc[2*w], l1 = loc[2*w+1];
        float e0 = fminf(fmaxf(l0 + (d0 + bd[0])*0.01f, 0.f), 1.f);
        float e1 = fminf(fmaxf(l1 + (d1 + bd[1])*0.01f, 0.f), 1.f);
        g_loc_extra[2*w]   = e0;
        g_loc_extra[2*w+1] = e1;
        int b = w / Ntok, n = w % Ntok;
        float* o1 = out_loc_base + ((size_t)b*2*Ntok + n)*2;
        o1[0] = l0; o1[1] = l1;
        float* o2 = out_loc_base + ((size_t)b*2*Ntok + Ntok + n)*2;
        o2[0] = e0; o2[1] = e1;
    }
}

// ---------------- K2: copy x into first-half tokens of output -----
__global__ void k_copyx(const float4* __restrict__ x, float4* __restrict__ out)
{
    size_t per = (size_t)Ntok*Dm/4;           // float4 per batch
    size_t i = (size_t)blockIdx.x*blockDim.x + threadIdx.x;
    if (i >= (size_t)Bsz*per) return;
    size_t b = i / per, rem = i % per;
    out[b*2*per + rem] = x[i];
}

// ---------------- K3: token2map scatter-add -----------------------
__global__ void k_scatter(const float* __restrict__ x, const float* __restrict__ loc)
{
    int w = (blockIdx.x*blockDim.x + threadIdx.x) >> 5;
    int lane = threadIdx.x & 31;
    if (w >= Bsz*Ntok) return;
    int b = w / Ntok;
    float lx = fminf(fmaxf(loc[2*w],   0.f), 1.f) * (float)(Wm-1);
    float ly = fminf(fmaxf(loc[2*w+1], 0.f), 1.f) * (float)(Hm-1);
    int xi = (int)rintf(lx);   // round-half-even, matches jnp.round
    int yi = (int)rintf(ly);
    size_t base = ((size_t)b*HWm + yi*Wm + xi) * 257;
    const float* xr = x + (size_t)w*Dm;
    for (int c = lane; c < 257; c += 32) {
        float val = (c < 256) ? xr[c] : 1.f;
        atomicAdd(&g_acc[base + c], val);
    }
}

// ---------------- K4: normalize scattered map ---------------------
__global__ void k_normmap()
{
    int p = (blockIdx.x*blockDim.x + threadIdx.x) >> 5;
    int lane = threadIdx.x & 31;
    if (p >= Bsz*HWm) return;
    size_t base = (size_t)p*257;
    float cnt = g_acc[base + 256];
    float msk = (cnt > 0.f) ? 1.f : 0.f;
    float inv = msk / (cnt + 1e-6f);
    for (int c = lane; c < 256; c += 32)
        g_feat[base + c] = g_acc[base + c] * inv;
    if (lane == 0) g_feat[base + 256] = msk;
}

// ---------------- K5: gaussian 3x3 + reconstruct ------------------
__global__ void k_recon()
{
    int pid = blockIdx.x;                  // 0 .. B*HW-1
    int b  = pid >> 14;
    int yx = pid & 16383;
    int y  = yx >> 7, x = yx & 127;
    int c  = threadIdx.x;                  // 0..255

    float e1 = expf(-0.125f), e2 = expf(-0.25f);
    float wsum = 1.f + 4.f*e1 + 4.f*e2;

    size_t pbase = ((size_t)b*HWm + yx)*257;
    float mask_c  = g_feat[pbase + 256];
    float feature = g_feat[pbase + c];
    float filt = 0.f, filtm = 0.f;
#pragma unroll
    for (int dy = -1; dy <= 1; dy++) {
        int ny = y + dy;
        if (ny < 0 || ny >= Hm) continue;
#pragma unroll
        for (int dx = -1; dx <= 1; dx++) {
            int nx = x + dx;
            if (nx < 0 || nx >= Wm) continue;
            int d2 = dy*dy + dx*dx;
            float wgt = ((d2 == 0) ? 1.f : (d2 == 1 ? e1 : e2)) / wsum;
            size_t nb = ((size_t)b*HWm + ny*Wm + nx)*257;
            filt  += wgt * g_feat[nb + c];
            filtm += wgt * g_feat[nb + 256];
        }
    }
    float f_i = filt / (filtm + 1e-6f);
    f_i = (filtm > 0.f) ? f_i : 0.f;
    g_fmap[((size_t)b*HWm + yx)*256 + c] = feature + (1.f - mask_c)*f_i;
}

// ---------------- K6: patch bilinear sample + conv + LN2 ----------
__device__ __forceinline__ float srctap(const float* sp, int xi, int yi, float w)
{
    if (xi < 0 || xi >= Wsrc || yi < 0 || yi >= Hsrc) return 0.f;
    return w * sp[yi*Wsrc + xi];
}

__global__ void k_patch(const float* __restrict__ src, const float* __restrict__ cw,
                        const float* __restrict__ cb,  const float* __restrict__ n2g,
                        const float* __restrict__ n2b)
{
    int tok = blockIdx.x;                  // 0..B*N-1
    int b = tok >> 14;
    int t = threadIdx.x;                   // 0..63
    __shared__ float patch[48];
    __shared__ float red[4];

    float lx = g_loc_extra[2*tok], ly = g_loc_extra[2*tok+1];
    if (t < 48) {
        int c = t >> 4, r = (t >> 2) & 3, col = t & 3;
        float gx = (lx + ((float)col - 1.5f)*(1.f/511.f)) * 512.f - 0.5f;
        float gy = (ly + ((float)r   - 1.5f)*(1.f/511.f)) * 512.f - 0.5f;
        float x0f = floorf(gx), y0f = floorf(gy);
        float wx = gx - x0f, wy = gy - y0f;
        int x0 = (int)x0f, y0 = (int)y0f;
        const float* sp = src + ((size_t)b*3 + c)*Hsrc*Wsrc;
        float v = srctap(sp, x0,   y0,   (1.f-wx)*(1.f-wy))
                + srctap(sp, x0+1, y0,   wx*(1.f-wy))
                + srctap(sp, x0,   y0+1, (1.f-wx)*wy)
                + srctap(sp, x0+1, y0+1, wx*wy);
        patch[t] = v;
    }
    __syncthreads();

    float acc = cb[t];
#pragma unroll
    for (int k = 0; k < 48; k++) acc += patch[k] * cw[t*48 + k];

    // LN over 64 values across the block (2 warps)
    float s = acc, sq = acc*acc;
#pragma unroll
    for (int o = 16; o > 0; o >>= 1) { s += __shfl_xor_sync(0xffffffffu, s, o); sq += __shfl_xor_sync(0xffffffffu, sq, o); }
    int wid = t >> 5;
    if ((t & 31) == 0) { red[wid] = s; red[2 + wid] = sq; }
    __syncthreads();
    s  = red[0] + red[1];
    sq = red[2] + red[3];
    float m   = s  * (1.f/64.f);
    float var = sq * (1.f/64.f) - m*m;
    float rr  = rsqrtf(var + 1e-5f);
    g_cat[(size_t)tok*CATD + 256 + t] = (acc - m)*rr*n2g[t] + n2b[t];
}

// ---------------- K7: bilinear gather from fmap -------------------
__global__ void k_gather()
{
    int tok = (blockIdx.x*blockDim.x + threadIdx.x) >> 5;
    int lane = threadIdx.x & 31;
    if (tok >= Bsz*Ntok) return;
    int b = tok >> 14;
    float gx = g_loc_extra[2*tok]   * 128.f - 0.5f;
    float gy = g_loc_extra[2*tok+1] * 128.f - 0.5f;
    float x0f = floorf(gx), y0f = floorf(gy);
    float wx = gx - x0f, wy = gy - y0f;
    int x0 = (int)x0f, y0 = (int)y0f;
    int x1 = x0 + 1,   y1 = y0 + 1;
    float vx0 = (x0 >= 0 && x0 < Wm) ? 1.f : 0.f;
    float vx1 = (x1 >= 0 && x1 < Wm) ? 1.f : 0.f;
    float vy0 = (y0 >= 0 && y0 < Hm) ? 1.f : 0.f;
    float vy1 = (y1 >= 0 && y1 < Hm) ? 1.f : 0.f;
    float w00 = (1.f-wx)*(1.f-wy)*vx0*vy0;
    float w10 = wx*(1.f-wy)*vx1*vy0;
    float w01 = (1.f-wx)*wy*vx0*vy1;
    float w11 = wx*wy*vx1*vy1;
    int cx0 = min(max(x0,0),Wm-1), cx1 = min(max(x1,0),Wm-1);
    int cy0 = min(max(y0,0),Hm-1), cy1 = min(max(y1,0),Hm-1);
    const float* base = g_fmap + (size_t)b*HWm*256;
    const float* p00 = base + (size_t)(cy0*Wm + cx0)*256;
    const float* p10 = base + (size_t)(cy0*Wm + cx1)*256;
    const float* p01 = base + (size_t)(cy1*Wm + cx0)*256;
    const float* p11 = base + (size_t)(cy1*Wm + cx1)*256;
    float* out = g_cat + (size_t)tok*CATD;
#pragma unroll
    for (int k = 0; k < 8; k++) {
        int c = lane + 32*k;
        out[c] = w00*p00[c] + w10*p10[c] + w01*p01[c] + w11*p11[c];
    }
}

// ---------------- K8/K9: tiled SGEMM (128x64x16), bias + epilogue -
// epi==0: C = gelu(A@B + bias)  -> g_hid        (A = g_cat,  K=320,  N=1024)
// epi==1: C = A@B + bias        -> out tokens   (A = g_hid,  K=1024, N=256)
#define BM 128
#define BN 64
#define BK 16
__global__ __launch_bounds__(256) void sgemm_k(const float* __restrict__ Bw,
                                               const float* __restrict__ bias,
                                               float* __restrict__ outp,
                                               int Nn, int K, int epi)
{
    __shared__ float As[BK][BM + 4];
    __shared__ float Bs[BK][BN + 4];
    const float* A = (epi == 0) ? g_cat : g_hid;
    float* C       = (epi == 0) ? g_hid : outp;

    int tid = threadIdx.x;
    int bm = blockIdx.y * BM, bn = blockIdx.x * BN;
    int ty = tid >> 4, tx = tid & 15;

    float acc[8][4];
#pragma unroll
    for (int i = 0; i < 8; i++)
#pragma unroll
        for (int j = 0; j < 4; j++) acc[i][j] = 0.f;

    const float* Ab = A + (size_t)bm * K;
    const float* Bb = Bw + bn;

    for (int k0 = 0; k0 < K; k0 += BK) {
        // load A tile 128x16 (512 float4, 2 per thread), store transposed
#pragma unroll
        for (int i = 0; i < 2; i++) {
            int idx = tid + i*256;
            int ar = idx >> 2;
            int ac = (idx & 3) * 4;
            float4 v = *(const float4*)(Ab + (size_t)ar*K + k0 + ac);
            As[ac+0][ar] = v.x; As[ac+1][ar] = v.y;
            As[ac+2][ar] = v.z; As[ac+3][ar] = v.w;
        }
        // load B tile 16x64 (256 float4, 1 per thread)
        {
            int br = tid >> 4;
            int bc = (tid & 15) * 4;
            float4 v = *(const float4*)(Bb + (size_t)(k0 + br)*Nn + bc);
            *(float4*)&Bs[br][bc] = v;
        }
        __syncthreads();
#pragma unroll
        for (int kk = 0; kk < BK; kk++) {
            float4 a4a = *(const float4*)&As[kk][ty*8];
            float4 a4b = *(const float4*)&As[kk][ty*8 + 4];
            float4 b4  = *(const float4*)&Bs[kk][tx*4];
            float a[8] = {a4a.x,a4a.y,a4a.z,a4a.w,a4b.x,a4b.y,a4b.z,a4b.w};
            float bb[4] = {b4.x,b4.y,b4.z,b4.w};
#pragma unroll
            for (int i = 0; i < 8; i++)
#pragma unroll
                for (int j = 0; j < 4; j++) acc[i][j] += a[i]*bb[j];
        }
        __syncthreads();
    }

#pragma unroll
    for (int i = 0; i < 8; i++) {
        int row = bm + ty*8 + i;
        size_t obase;
        if (epi == 0) {
            obase = (size_t)row * Nn;
        } else {
            int b = row >> 14, n = row & 16383;
            obase = (((size_t)b*2*Ntok) + Ntok + n) * 256;
        }
#pragma unroll
        for (int j = 0; j < 4; j++) {
            int col = bn + tx*4 + j;
            float v = acc[i][j] + bias[col];
            if (epi == 0) v = 0.5f*v*(1.f + erff(v*0.70710678118654752f));
            C[obase + col] = v;
        }
    }
}

// ---------------- launch -------------------------------------------
extern "C" void kernel_launch(void* const* d_in, const int* in_sizes, int n_in,
                              void* d_out, int out_size)
{
    (void)in_sizes; (void)n_in; (void)out_size;
    const float* x      = (const float*)d_in[0];
    const float* loc    = (const float*)d_in[1];
    const float* src    = (const float*)d_in[2];
    // d_in[3] pos_embed, d_in[4] H, d_in[5] W, d_in[6] kernel_size (fixed)
    const float* w_delta = (const float*)d_in[7];
    const float* b_delta = (const float*)d_in[8];
    const float* n1g    = (const float*)d_in[9];
    const float* n1b    = (const float*)d_in[10];
    const float* conv_w = (const float*)d_in[11];
    const float* conv_b = (const float*)d_in[12];
    const float* n2g    = (const float*)d_in[13];
    const float* n2b    = (const float*)d_in[14];
    const float* fc1w   = (const float*)d_in[15];
    const float* fc1b   = (const float*)d_in[16];
    const float* fc2w   = (const float*)d_in[17];
    const float* fc2b   = (const float*)d_in[18];
    float* out = (float*)d_out;
    float* out_loc = out + (size_t)Bsz*2*Ntok*Dm;

    // zero scatter accumulator
    {
        size_t n4 = (size_t)Bsz*HWm*257/4;
        k_zero_acc<<<(unsigned)((n4 + 255)/256), 256>>>();
    }
    // delta / loc_extra / loc outputs
    k_delta<<<Bsz*Ntok/8, 256>>>(x, loc, w_delta, b_delta, n1g, n1b, out_loc);
    // copy x -> output first-half tokens
    {
        size_t n4 = (size_t)Bsz*Ntok*Dm/4;
        k_copyx<<<(unsigned)((n4 + 255)/256), 256>>>((const float4*)x, (float4*)out);
    }
    // token2map
    k_scatter<<<Bsz*Ntok/8, 256>>>(x, loc);
    k_normmap<<<Bsz*HWm/8, 256>>>();
    k_recon<<<Bsz*HWm, 256>>>();
    // patch conv + LN2 (needs loc_extra)
    k_patch<<<Bsz*Ntok, 64>>>(src, conv_w, conv_b, n2g, n2b);
    // gather extra_inter (needs fmap + loc_extra)
    k_gather<<<Bsz*Ntok/8, 256>>>();
    // MLP
    sgemm_k<<<dim3(HIDD/BN, Bsz*Ntok/BM), 256>>>(fc1w, fc1b, nullptr, HIDD, CATD, 0);
    sgemm_k<<<dim3(Dm/BN,   Bsz*Ntok/BM), 256>>>(fc2w, fc2b, out,     Dm,   HIDD, 1);
}

// round 3
// speedup vs baseline: 1.5887x; 1.5887x over previous
#include <cuda_runtime.h>
#include <cuda_bf16.h>
#include <math.h>
#include <stdint.h>

// ---------------- problem constants (fixed shapes) ----------------
#define Bsz   4
#define Ntok  16384
#define Dm    256
#define LDm   64
#define Hm    128
#define Wm    128
#define HWm   (Hm*Wm)
#define Hsrc  512
#define Wsrc  512
#define CATD  320
#define HIDD  1024
#define Mrows (Bsz*Ntok)

// ---------------- scratch (static device globals; no allocs) ------
__device__ __align__(16) float g_loc_extra[Bsz*Ntok*2];
__device__ __align__(16) float g_acc [Bsz*HWm*257];
__device__ __align__(16) float g_feat[Bsz*HWm*257];
__device__ __align__(16) float g_fmap[(size_t)Bsz*HWm*256];
__device__ __align__(16) __nv_bfloat16 g_cat_hi[(size_t)Mrows*CATD];
__device__ __align__(16) __nv_bfloat16 g_cat_lo[(size_t)Mrows*CATD];
__device__ __align__(16) __nv_bfloat16 g_hid_hi[(size_t)Mrows*HIDD];
__device__ __align__(16) __nv_bfloat16 g_hid_lo[(size_t)Mrows*HIDD];
__device__ __align__(16) __nv_bfloat16 g_w1h[(size_t)HIDD*CATD];
__device__ __align__(16) __nv_bfloat16 g_w1l[(size_t)HIDD*CATD];
__device__ __align__(16) __nv_bfloat16 g_w2h[(size_t)Dm*HIDD];
__device__ __align__(16) __nv_bfloat16 g_w2l[(size_t)Dm*HIDD];

// ================= PTX helpers (base sm_80+ features only) ==========
__device__ __forceinline__ uint32_t smem_u32(const void* p) {
    uint32_t a;
    asm("{ .reg .u64 t; cvta.to.shared.u64 t, %1; cvt.u32.u64 %0, t; }" : "=r"(a) : "l"(p));
    return a;
}
#define CP16(smem, gptr) \
    asm volatile("cp.async.cg.shared.global [%0], [%1], 16;" :: "r"(smem), "l"(gptr) : "memory")
#define CP_COMMIT() asm volatile("cp.async.commit_group;" ::: "memory")
#define CP_WAIT1()  asm volatile("cp.async.wait_group 1;" ::: "memory")

__device__ __forceinline__ void ldsm4(uint32_t* r, uint32_t addr) {
    asm volatile("ldmatrix.sync.aligned.m8n8.x4.shared.b16 {%0,%1,%2,%3}, [%4];"
        : "=r"(r[0]), "=r"(r[1]), "=r"(r[2]), "=r"(r[3]) : "r"(addr));
}
__device__ __forceinline__ void ldsm2(uint32_t* r, uint32_t addr) {
    asm volatile("ldmatrix.sync.aligned.m8n8.x2.shared.b16 {%0,%1}, [%2];"
        : "=r"(r[0]), "=r"(r[1]) : "r"(addr));
}
__device__ __forceinline__ void mma16816(float* d, const uint32_t* a, const uint32_t* b) {
    asm volatile("mma.sync.aligned.m16n8k16.row.col.f32.bf16.bf16.f32 "
        "{%0,%1,%2,%3}, {%4,%5,%6,%7}, {%8,%9}, {%0,%1,%2,%3};"
        : "+f"(d[0]), "+f"(d[1]), "+f"(d[2]), "+f"(d[3])
        : "r"(a[0]), "r"(a[1]), "r"(a[2]), "r"(a[3]), "r"(b[0]), "r"(b[1]));
}
__device__ __forceinline__ void split_bf16(float v, __nv_bfloat16& h, __nv_bfloat16& l) {
    h = __float2bfloat16(v);
    l = __float2bfloat16(v - __bfloat162float(h));
}

// ---------------- K0: zero the scatter accumulator ----------------
__global__ void k_zero_acc() {
    size_t n4 = (size_t)Bsz*HWm*257/4;
    size_t i = (size_t)blockIdx.x*blockDim.x + threadIdx.x;
    if (i < n4) ((float4*)g_acc)[i] = make_float4(0.f,0.f,0.f,0.f);
}

// ---------------- K1: LN1 + delta + loc_extra + loc outputs -------
__global__ void k_delta(const float* __restrict__ x, const float* __restrict__ loc,
                        const float* __restrict__ wd, const float* __restrict__ bd,
                        const float* __restrict__ n1g, const float* __restrict__ n1b,
                        float* __restrict__ out_loc_base)
{
    int w = (blockIdx.x*blockDim.x + threadIdx.x) >> 5;
    int lane = threadIdx.x & 31;
    if (w >= Bsz*Ntok) return;
    const float* xr = x + (size_t)w*Dm;
    float v[8], s = 0.f, sq = 0.f;
#pragma unroll
    for (int k = 0; k < 8; k++) { v[k] = xr[lane + 32*k]; s += v[k]; sq += v[k]*v[k]; }
#pragma unroll
    for (int o = 16; o > 0; o >>= 1) { s += __shfl_xor_sync(0xffffffffu, s, o); sq += __shfl_xor_sync(0xffffffffu, sq, o); }
    float m   = s  * (1.f/256.f);
    float var = sq * (1.f/256.f) - m*m;
    float r   = rsqrtf(var + 1e-5f);
    float d0 = 0.f, d1 = 0.f;
#pragma unroll
    for (int k = 0; k < 8; k++) {
        int c = lane + 32*k;
        float y = (v[k]-m)*r*n1g[c] + n1b[c];
        d0 += y * wd[2*c];
        d1 += y * wd[2*c+1];
    }
#pragma unroll
    for (int o = 16; o > 0; o >>= 1) { d0 += __shfl_xor_sync(0xffffffffu, d0, o); d1 += __shfl_xor_sync(0xffffffffu, d1, o); }
    if (lane == 0) {
        float l0 = loc[2*w], l1 = loc[2*w+1];
        float e0 = fminf(fmaxf(l0 + (d0 + bd[0])*0.01f, 0.f), 1.f);
        float e1 = fminf(fmaxf(l1 + (d1 + bd[1])*0.01f, 0.f), 1.f);
        g_loc_extra[2*w]   = e0;
        g_loc_extra[2*w+1] = e1;
        int b = w / Ntok, n = w % Ntok;
        float* o1 = out_loc_base + ((size_t)b*2*Ntok + n)*2;
        o1[0] = l0; o1[1] = l1;
        float* o2 = out_loc_base + ((size_t)b*2*Ntok + Ntok + n)*2;
        o2[0] = e0; o2[1] = e1;
    }
}

// ---------------- K2: copy x into first-half tokens of output -----
__global__ void k_copyx(const float4* __restrict__ x, float4* __restrict__ out)
{
    size_t per = (size_t)Ntok*Dm/4;
    size_t i = (size_t)blockIdx.x*blockDim.x + threadIdx.x;
    if (i >= (size_t)Bsz*per) return;
    size_t b = i / per, rem = i % per;
    out[b*2*per + rem] = x[i];
}

// ---------------- K3: token2map scatter-add -----------------------
__global__ void k_scatter(const float* __restrict__ x, const float* __restrict__ loc)
{
    int w = (blockIdx.x*blockDim.x + threadIdx.x) >> 5;
    int lane = threadIdx.x & 31;
    if (w >= Bsz*Ntok) return;
    int b = w / Ntok;
    float lx = fminf(fmaxf(loc[2*w],   0.f), 1.f) * (float)(Wm-1);
    float ly = fminf(fmaxf(loc[2*w+1], 0.f), 1.f) * (float)(Hm-1);
    int xi = (int)rintf(lx);
    int yi = (int)rintf(ly);
    size_t base = ((size_t)b*HWm + yi*Wm + xi) * 257;
    const float* xr = x + (size_t)w*Dm;
    for (int c = lane; c < 257; c += 32) {
        float val = (c < 256) ? xr[c] : 1.f;
        atomicAdd(&g_acc[base + c], val);
    }
}

// ---------------- K4: normalize scattered map ---------------------
__global__ void k_normmap()
{
    int p = (blockIdx.x*blockDim.x + threadIdx.x) >> 5;
    int lane = threadIdx.x & 31;
    if (p >= Bsz*HWm) return;
    size_t base = (size_t)p*257;
    float cnt = g_acc[base + 256];
    float msk = (cnt > 0.f) ? 1.f : 0.f;
    float inv = msk / (cnt + 1e-6f);
    for (int c = lane; c < 256; c += 32)
        g_feat[base + c] = g_acc[base + c] * inv;
    if (lane == 0) g_feat[base + 256] = msk;
}

// ---------------- K5: gaussian 3x3 + reconstruct ------------------
__global__ void k_recon()
{
    int pid = blockIdx.x;
    int b  = pid >> 14;
    int yx = pid & 16383;
    int y  = yx >> 7, x = yx & 127;
    int c  = threadIdx.x;

    float e1 = expf(-0.125f), e2 = expf(-0.25f);
    float wsum = 1.f + 4.f*e1 + 4.f*e2;

    size_t pbase = ((size_t)b*HWm + yx)*257;
    float mask_c  = g_feat[pbase + 256];
    float feature = g_feat[pbase + c];
    float filt = 0.f, filtm = 0.f;
#pragma unroll
    for (int dy = -1; dy <= 1; dy++) {
        int ny = y + dy;
        if (ny < 0 || ny >= Hm) continue;
#pragma unroll
        for (int dx = -1; dx <= 1; dx++) {
            int nx = x + dx;
            if (nx < 0 || nx >= Wm) continue;
            int d2 = dy*dy + dx*dx;
            float wgt = ((d2 == 0) ? 1.f : (d2 == 1 ? e1 : e2)) / wsum;
            size_t nb = ((size_t)b*HWm + ny*Wm + nx)*257;
            filt  += wgt * g_feat[nb + c];
            filtm += wgt * g_feat[nb + 256];
        }
    }
    float f_i = filt / (filtm + 1e-6f);
    f_i = (filtm > 0.f) ? f_i : 0.f;
    g_fmap[((size_t)b*HWm + yx)*256 + c] = feature + (1.f - mask_c)*f_i;
}

// ---------------- K6: patch bilinear sample + conv + LN2 ----------
__device__ __forceinline__ float srctap(const float* sp, int xi, int yi, float w)
{
    if (xi < 0 || xi >= Wsrc || yi < 0 || yi >= Hsrc) return 0.f;
    return w * sp[yi*Wsrc + xi];
}

__global__ void k_patch(const float* __restrict__ src, const float* __restrict__ cw,
                        const float* __restrict__ cb,  const float* __restrict__ n2g,
                        const float* __restrict__ n2b)
{
    int tok = blockIdx.x;
    int b = tok >> 14;
    int t = threadIdx.x;
    __shared__ float patch[48];
    __shared__ float red[4];

    float lx = g_loc_extra[2*tok], ly = g_loc_extra[2*tok+1];
    if (t < 48) {
        int c = t >> 4, r = (t >> 2) & 3, col = t & 3;
        float gx = (lx + ((float)col - 1.5f)*(1.f/511.f)) * 512.f - 0.5f;
        float gy = (ly + ((float)r   - 1.5f)*(1.f/511.f)) * 512.f - 0.5f;
        float x0f = floorf(gx), y0f = floorf(gy);
        float wx = gx - x0f, wy = gy - y0f;
        int x0 = (int)x0f, y0 = (int)y0f;
        const float* sp = src + ((size_t)b*3 + c)*Hsrc*Wsrc;
        float v = srctap(sp, x0,   y0,   (1.f-wx)*(1.f-wy))
                + srctap(sp, x0+1, y0,   wx*(1.f-wy))
                + srctap(sp, x0,   y0+1, (1.f-wx)*wy)
                + srctap(sp, x0+1, y0+1, wx*wy);
        patch[t] = v;
    }
    __syncthreads();

    float acc = cb[t];
#pragma unroll
    for (int k = 0; k < 48; k++) acc += patch[k] * cw[t*48 + k];

    float s = acc, sq = acc*acc;
#pragma unroll
    for (int o = 16; o > 0; o >>= 1) { s += __shfl_xor_sync(0xffffffffu, s, o); sq += __shfl_xor_sync(0xffffffffu, sq, o); }
    int wid = t >> 5;
    if ((t & 31) == 0) { red[wid] = s; red[2 + wid] = sq; }
    __syncthreads();
    s  = red[0] + red[1];
    sq = red[2] + red[3];
    float m   = s  * (1.f/64.f);
    float var = sq * (1.f/64.f) - m*m;
    float rr  = rsqrtf(var + 1e-5f);
    float v = (acc - m)*rr*n2g[t] + n2b[t];
    __nv_bfloat16 h, l; split_bf16(v, h, l);
    g_cat_hi[(size_t)tok*CATD + 256 + t] = h;
    g_cat_lo[(size_t)tok*CATD + 256 + t] = l;
}

// ---------------- K7: bilinear gather from fmap -> cat hi/lo ------
__global__ void k_gather()
{
    int tok = (blockIdx.x*blockDim.x + threadIdx.x) >> 5;
    int lane = threadIdx.x & 31;
    if (tok >= Bsz*Ntok) return;
    int b = tok >> 14;
    float gx = g_loc_extra[2*tok]   * 128.f - 0.5f;
    float gy = g_loc_extra[2*tok+1] * 128.f - 0.5f;
    float x0f = floorf(gx), y0f = floorf(gy);
    float wx = gx - x0f, wy = gy - y0f;
    int x0 = (int)x0f, y0 = (int)y0f;
    int x1 = x0 + 1,   y1 = y0 + 1;
    float vx0 = (x0 >= 0 && x0 < Wm) ? 1.f : 0.f;
    float vx1 = (x1 >= 0 && x1 < Wm) ? 1.f : 0.f;
    float vy0 = (y0 >= 0 && y0 < Hm) ? 1.f : 0.f;
    float vy1 = (y1 >= 0 && y1 < Hm) ? 1.f : 0.f;
    float w00 = (1.f-wx)*(1.f-wy)*vx0*vy0;
    float w10 = wx*(1.f-wy)*vx1*vy0;
    float w01 = (1.f-wx)*wy*vx0*vy1;
    float w11 = wx*wy*vx1*vy1;
    int cx0 = min(max(x0,0),Wm-1), cx1 = min(max(x1,0),Wm-1);
    int cy0 = min(max(y0,0),Hm-1), cy1 = min(max(y1,0),Hm-1);
    const float* base = g_fmap + (size_t)b*HWm*256;
    const float* p00 = base + (size_t)(cy0*Wm + cx0)*256;
    const float* p10 = base + (size_t)(cy0*Wm + cx1)*256;
    const float* p01 = base + (size_t)(cy1*Wm + cx0)*256;
    const float* p11 = base + (size_t)(cy1*Wm + cx1)*256;
    size_t obase = (size_t)tok*CATD;
#pragma unroll
    for (int k = 0; k < 8; k++) {
        int c = lane + 32*k;
        float v = w00*p00[c] + w10*p10[c] + w01*p01[c] + w11*p11[c];
        __nv_bfloat16 h, l; split_bf16(v, h, l);
        g_cat_hi[obase + c] = h;
        g_cat_lo[obase + c] = l;
    }
}

// ---------------- weight transpose + bf16 split: [K][N] -> [N][K] --
__global__ void k_wsplit(const float* __restrict__ in, int K, int N, int which)
{
    __nv_bfloat16* oh = which ? g_w2h : g_w1h;
    __nv_bfloat16* ol = which ? g_w2l : g_w1l;
    __shared__ float t[32][33];
    int k0 = blockIdx.y*32, n0 = blockIdx.x*32;
    int x = threadIdx.x, y = threadIdx.y;
#pragma unroll
    for (int i = 0; i < 32; i += 8)
        t[y+i][x] = in[(size_t)(k0+y+i)*N + n0 + x];
    __syncthreads();
#pragma unroll
    for (int i = 0; i < 32; i += 8) {
        float v = t[x][y+i];                    // in[k0+x][n0+y+i]
        __nv_bfloat16 h, l; split_bf16(v, h, l);
        oh[(size_t)(n0+y+i)*K + k0 + x] = h;
        ol[(size_t)(n0+y+i)*K + k0 + x] = l;
    }
}

// ---------------- HMMA bf16 split GEMM (128x128 CTA, K-chunk 32) ---
// epi==0: gelu(cat @ w1^T + b1) -> hid_hi/lo bf16     (K=320,  Nn=1024)
// epi==1:       hid @ w2^T + b2 -> out (row-remapped) (K=1024, Nn=256)
// SMEM stage: Ah|Al|Bh|Bl, each 128 rows x 32 bf16, row stride 80B (10240B).
#define STG   40960
#define NSTG  3
#define GEMM_SMEM (NSTG*STG)

__global__ __launch_bounds__(256) void mma_gemm(const float* __restrict__ bias,
                                                float* __restrict__ outp,
                                                int K, int Nn, int epi)
{
    extern __shared__ char smem[];
    uint32_t sb = smem_u32(smem);

    const __nv_bfloat16 *Ah, *Al, *Bh, *Bl;
    if (epi == 0) { Ah = g_cat_hi; Al = g_cat_lo; Bh = g_w1h; Bl = g_w1l; }
    else          { Ah = g_hid_hi; Al = g_hid_lo; Bh = g_w2h; Bl = g_w2l; }

    int tid = threadIdx.x, lane = tid & 31, wid = tid >> 5;
    int warpM = wid & 1, warpN = wid >> 1;
    int bm = blockIdx.y*128, bn = blockIdx.x*128;
    int nch = K >> 5;

    const __nv_bfloat16* Abase = Ah + (size_t)bm*K;
    const __nv_bfloat16* Albase = Al + (size_t)bm*K;
    const __nv_bfloat16* Bbase = Bh + (size_t)bn*K;
    const __nv_bfloat16* Blbase = Bl + (size_t)bn*K;

    float acc[4][4][4];
#pragma unroll
    for (int a = 0; a < 4; a++)
#pragma unroll
        for (int b = 0; b < 4; b++)
#pragma unroll
            for (int c = 0; c < 4; c++) acc[a][b][c] = 0.f;

    // ---- async chunk loader (8x cp.async 16B per thread) ----
#define LOAD_CHUNK(i) do { \
    int _k0 = (i) << 5; \
    uint32_t _st = sb + ((i) % NSTG) * STG; \
    _Pragma("unroll") \
    for (int _j = 0; _j < 2; _j++) { \
        int _u = tid + _j*256; \
        int _r = _u >> 2, _kb = _u & 3; \
        size_t _go = (size_t)_r*K + _k0 + _kb*8; \
        uint32_t _do_ = (uint32_t)(_r*80 + _kb*16); \
        CP16(_st + _do_,          Abase  + _go); \
        CP16(_st + 10240 + _do_,  Albase + _go); \
        CP16(_st + 20480 + _do_,  Bbase  + _go); \
        CP16(_st + 30720 + _do_,  Blbase + _go); \
    } \
} while (0)

    // prologue: 2 chunks in flight
    LOAD_CHUNK(0); CP_COMMIT();
    if (nch > 1) LOAD_CHUNK(1);
    CP_COMMIT();

    // ldmatrix address components
    int arow = warpM*64 + (lane & 7) + ((lane >> 3) & 1)*8;   // + mf*16
    uint32_t akb = ((lane >> 4) & 1)*16;                      // + kstep*32
    int lane16 = lane & 15;
    int brow = warpN*32 + (lane16 & 7);                       // + nf*8
    uint32_t bkb = ((lane16 >> 3) & 1)*16;

    for (int i = 0; i < nch; i++) {
        CP_WAIT1();
        __syncthreads();
        if (i + 2 < nch) LOAD_CHUNK(i + 2);
        CP_COMMIT();

        uint32_t st = sb + (i % NSTG)*STG;
#pragma unroll
        for (int ks = 0; ks < 2; ks++) {
            uint32_t kB = ks*32;
            uint32_t a4[4][4], l4[4][4], b2[4][2], c2[4][2];
#pragma unroll
            for (int mf = 0; mf < 4; mf++) {
                ldsm4(a4[mf], st +         (uint32_t)(arow + mf*16)*80 + akb + kB);
                ldsm4(l4[mf], st + 10240 + (uint32_t)(arow + mf*16)*80 + akb + kB);
            }
#pragma unroll
            for (int nf = 0; nf < 4; nf++) {
                ldsm2(b2[nf], st + 20480 + (uint32_t)(brow + nf*8)*80 + bkb + kB);
                ldsm2(c2[nf], st + 30720 + (uint32_t)(brow + nf*8)*80 + bkb + kB);
            }
#pragma unroll
            for (int mf = 0; mf < 4; mf++)
#pragma unroll
                for (int nf = 0; nf < 4; nf++) {
                    mma16816(acc[mf][nf], a4[mf], b2[nf]);
                    mma16816(acc[mf][nf], a4[mf], c2[nf]);
                    mma16816(acc[mf][nf], l4[mf], b2[nf]);
                }
        }
    }

    // ---- epilogue ----
    int r0 = bm + warpM*64 + (lane >> 2);
    int cbase = bn + warpN*32 + (lane & 3)*2;
#pragma unroll
    for (int mf = 0; mf < 4; mf++) {
        int row0 = r0 + mf*16;
        int row1 = row0 + 8;
#pragma unroll
        for (int nf = 0; nf < 4; nf++) {
            int col = cbase + nf*8;
            float b0 = bias[col], b1 = bias[col + 1];
            float v00 = acc[mf][nf][0] + b0;
            float v01 = acc[mf][nf][1] + b1;
            float v10 = acc[mf][nf][2] + b0;
            float v11 = acc[mf][nf][3] + b1;
            if (epi == 0) {
                v00 = 0.5f*v00*(1.f + erff(v00*0.70710678118654752f));
                v01 = 0.5f*v01*(1.f + erff(v01*0.70710678118654752f));
                v10 = 0.5f*v10*(1.f + erff(v10*0.70710678118654752f));
                v11 = 0.5f*v11*(1.f + erff(v11*0.70710678118654752f));
                __nv_bfloat16 h0,l0,h1,l1;
                split_bf16(v00,h0,l0); split_bf16(v01,h1,l1);
                *(__nv_bfloat162*)(g_hid_hi + (size_t)row0*HIDD + col) = __nv_bfloat162(h0,h1);
                *(__nv_bfloat162*)(g_hid_lo + (size_t)row0*HIDD + col) = __nv_bfloat162(l0,l1);
                split_bf16(v10,h0,l0); split_bf16(v11,h1,l1);
                *(__nv_bfloat162*)(g_hid_hi + (size_t)row1*HIDD + col) = __nv_bfloat162(h0,h1);
                *(__nv_bfloat162*)(g_hid_lo + (size_t)row1*HIDD + col) = __nv_bfloat162(l0,l1);
            } else {
                int bb0 = row0 >> 14, n0 = row0 & 16383;
                int bb1 = row1 >> 14, n1 = row1 & 16383;
                size_t ob0 = (((size_t)bb0*2*Ntok) + Ntok + n0)*256;
                size_t ob1 = (((size_t)bb1*2*Ntok) + Ntok + n1)*256;
                *(float2*)(outp + ob0 + col) = make_float2(v00, v01);
                *(float2*)(outp + ob1 + col) = make_float2(v10, v11);
            }
        }
    }
}

// ---------------- launch -------------------------------------------
extern "C" void kernel_launch(void* const* d_in, const int* in_sizes, int n_in,
                              void* d_out, int out_size)
{
    (void)in_sizes; (void)n_in; (void)out_size;
    const float* x      = (const float*)d_in[0];
    const float* loc    = (const float*)d_in[1];
    const float* src    = (const float*)d_in[2];
    const float* w_delta = (const float*)d_in[7];
    const float* b_delta = (const float*)d_in[8];
    const float* n1g    = (const float*)d_in[9];
    const float* n1b    = (const float*)d_in[10];
    const float* conv_w = (const float*)d_in[11];
    const float* conv_b = (const float*)d_in[12];
    const float* n2g    = (const float*)d_in[13];
    const float* n2b    = (const float*)d_in[14];
    const float* fc1w   = (const float*)d_in[15];
    const float* fc1b   = (const float*)d_in[16];
    const float* fc2w   = (const float*)d_in[17];
    const float* fc2b   = (const float*)d_in[18];
    float* out = (float*)d_out;
    float* out_loc = out + (size_t)Bsz*2*Ntok*Dm;

    cudaFuncSetAttribute(mma_gemm, cudaFuncAttributeMaxDynamicSharedMemorySize, GEMM_SMEM);

    // weight transpose+split (independent of data path)
    k_wsplit<<<dim3(HIDD/32, CATD/32), dim3(32,8)>>>(fc1w, CATD, HIDD, 0);
    k_wsplit<<<dim3(Dm/32,  HIDD/32), dim3(32,8)>>>(fc2w, HIDD, Dm, 1);

    // zero scatter accumulator
    {
        size_t n4 = (size_t)Bsz*HWm*257/4;
        k_zero_acc<<<(unsigned)((n4 + 255)/256), 256>>>();
    }
    k_delta<<<Bsz*Ntok/8, 256>>>(x, loc, w_delta, b_delta, n1g, n1b, out_loc);
    {
        size_t n4 = (size_t)Bsz*Ntok*Dm/4;
        k_copyx<<<(unsigned)((n4 + 255)/256), 256>>>((const float4*)x, (float4*)out);
    }
    k_scatter<<<Bsz*Ntok/8, 256>>>(x, loc);
    k_normmap<<<Bsz*HWm/8, 256>>>();
    k_recon<<<Bsz*HWm, 256>>>();
    k_patch<<<Bsz*Ntok, 64>>>(src, conv_w, conv_b, n2g, n2b);
    k_gather<<<Bsz*Ntok/8, 256>>>();

    // MLP on tensor cores (bf16 3-term hi/lo split, fp32 accumulate)
    mma_gemm<<<dim3(HIDD/128, Mrows/128), 256, GEMM_SMEM>>>(fc1b, nullptr, CATD, HIDD, 0);
    mma_gemm<<<dim3(Dm/128,   Mrows/128), 256, GEMM_SMEM>>>(fc2b, out,     HIDD, Dm,   1);
}

// round 4
// speedup vs baseline: 2.0088x; 1.2644x over previous
#include <cuda_runtime.h>
#include <cuda_fp16.h>
#include <math.h>
#include <stdint.h>

// ---------------- problem constants (fixed shapes) ----------------
#define Bsz   4
#define Ntok  16384
#define Dm    256
#define LDm   64
#define Hm    128
#define Wm    128
#define HWm   (Hm*Wm)
#define Hsrc  512
#define Wsrc  512
#define CATD  320
#define HIDD  1024
#define Mrows (Bsz*Ntok)

// ---------------- scratch (static device globals; no allocs) ------
__device__ __align__(16) float g_loc_extra[Bsz*Ntok*2];
__device__ __align__(16) float g_acc [Bsz*HWm*257];
__device__ __align__(16) float g_feat[Bsz*HWm*257];
__device__ __align__(16) float g_fmap[(size_t)Bsz*HWm*256];
__device__ __align__(16) __half g_cat_hi[(size_t)Mrows*CATD];
__device__ __align__(16) __half g_cat_lo[(size_t)Mrows*CATD];
__device__ __align__(16) __half g_hid_hi[(size_t)Mrows*HIDD];
__device__ __align__(16) __half g_hid_lo[(size_t)Mrows*HIDD];
__device__ __align__(16) __half g_w1[(size_t)HIDD*CATD];     // fc1_w^T fp16 [N][K]
__device__ __align__(16) __half g_w2[(size_t)Dm*HIDD];       // fc2_w^T fp16 [N][K]

// ================= PTX helpers (base sm_80+ features only) ==========
__device__ __forceinline__ uint32_t smem_u32(const void* p) {
    uint32_t a;
    asm("{ .reg .u64 t; cvta.to.shared.u64 t, %1; cvt.u32.u64 %0, t; }" : "=r"(a) : "l"(p));
    return a;
}
#define CP16(smem, gptr) \
    asm volatile("cp.async.cg.shared.global [%0], [%1], 16;" :: "r"(smem), "l"(gptr) : "memory")
#define CP_COMMIT() asm volatile("cp.async.commit_group;" ::: "memory")
#define CP_WAIT1()  asm volatile("cp.async.wait_group 1;" ::: "memory")

__device__ __forceinline__ void ldsm4(uint32_t* r, uint32_t addr) {
    asm volatile("ldmatrix.sync.aligned.m8n8.x4.shared.b16 {%0,%1,%2,%3}, [%4];"
        : "=r"(r[0]), "=r"(r[1]), "=r"(r[2]), "=r"(r[3]) : "r"(addr));
}
__device__ __forceinline__ void mma16816(float* d, const uint32_t* a, const uint32_t* b) {
    asm volatile("mma.sync.aligned.m16n8k16.row.col.f32.f16.f16.f32 "
        "{%0,%1,%2,%3}, {%4,%5,%6,%7}, {%8,%9}, {%0,%1,%2,%3};"
        : "+f"(d[0]), "+f"(d[1]), "+f"(d[2]), "+f"(d[3])
        : "r"(a[0]), "r"(a[1]), "r"(a[2]), "r"(a[3]), "r"(b[0]), "r"(b[1]));
}
__device__ __forceinline__ void split_h16(float v, __half& h, __half& l) {
    h = __float2half_rn(v);
    l = __float2half_rn(v - __half2float(h));
}

// ---------------- K0: zero the scatter accumulator ----------------
__global__ void k_zero_acc() {
    size_t n4 = (size_t)Bsz*HWm*257/4;
    size_t i = (size_t)blockIdx.x*blockDim.x + threadIdx.x;
    if (i < n4) ((float4*)g_acc)[i] = make_float4(0.f,0.f,0.f,0.f);
}

// ---------------- K1: LN1 + delta + loc_extra + loc outputs -------
__global__ void k_delta(const float* __restrict__ x, const float* __restrict__ loc,
                        const float* __restrict__ wd, const float* __restrict__ bd,
                        const float* __restrict__ n1g, const float* __restrict__ n1b,
                        float* __restrict__ out_loc_base)
{
    int w = (blockIdx.x*blockDim.x + threadIdx.x) >> 5;
    int lane = threadIdx.x & 31;
    if (w >= Bsz*Ntok) return;
    const float* xr = x + (size_t)w*Dm;
    float v[8], s = 0.f, sq = 0.f;
#pragma unroll
    for (int k = 0; k < 8; k++) { v[k] = xr[lane + 32*k]; s += v[k]; sq += v[k]*v[k]; }
#pragma unroll
    for (int o = 16; o > 0; o >>= 1) { s += __shfl_xor_sync(0xffffffffu, s, o); sq += __shfl_xor_sync(0xffffffffu, sq, o); }
    float m   = s  * (1.f/256.f);
    float var = sq * (1.f/256.f) - m*m;
    float r   = rsqrtf(var + 1e-5f);
    float d0 = 0.f, d1 = 0.f;
#pragma unroll
    for (int k = 0; k < 8; k++) {
        int c = lane + 32*k;
        float y = (v[k]-m)*r*n1g[c] + n1b[c];
        d0 += y * wd[2*c];
        d1 += y * wd[2*c+1];
    }
#pragma unroll
    for (int o = 16; o > 0; o >>= 1) { d0 += __shfl_xor_sync(0xffffffffu, d0, o); d1 += __shfl_xor_sync(0xffffffffu, d1, o); }
    if (lane == 0) {
        float l0 = loc[2*w], l1 = loc[2*w+1];
        float e0 = fminf(fmaxf(l0 + (d0 + bd[0])*0.01f, 0.f), 1.f);
        float e1 = fminf(fmaxf(l1 + (d1 + bd[1])*0.01f, 0.f), 1.f);
        g_loc_extra[2*w]   = e0;
        g_loc_extra[2*w+1] = e1;
        int b = w / Ntok, n = w % Ntok;
        float* o1 = out_loc_base + ((size_t)b*2*Ntok + n)*2;
        o1[0] = l0; o1[1] = l1;
        float* o2 = out_loc_base + ((size_t)b*2*Ntok + Ntok + n)*2;
        o2[0] = e0; o2[1] = e1;
    }
}

// ---------------- K2: copy x into first-half tokens of output -----
__global__ void k_copyx(const float4* __restrict__ x, float4* __restrict__ out)
{
    size_t per = (size_t)Ntok*Dm/4;
    size_t i = (size_t)blockIdx.x*blockDim.x + threadIdx.x;
    if (i >= (size_t)Bsz*per) return;
    size_t b = i / per, rem = i % per;
    out[b*2*per + rem] = x[i];
}

// ---------------- K3: token2map scatter-add -----------------------
__global__ void k_scatter(const float* __restrict__ x, const float* __restrict__ loc)
{
    int w = (blockIdx.x*blockDim.x + threadIdx.x) >> 5;
    int lane = threadIdx.x & 31;
    if (w >= Bsz*Ntok) return;
    int b = w / Ntok;
    float lx = fminf(fmaxf(loc[2*w],   0.f), 1.f) * (float)(Wm-1);
    float ly = fminf(fmaxf(loc[2*w+1], 0.f), 1.f) * (float)(Hm-1);
    int xi = (int)rintf(lx);
    int yi = (int)rintf(ly);
    size_t base = ((size_t)b*HWm + yi*Wm + xi) * 257;
    const float* xr = x + (size_t)w*Dm;
    for (int c = lane; c < 257; c += 32) {
        float val = (c < 256) ? xr[c] : 1.f;
        atomicAdd(&g_acc[base + c], val);
    }
}

// ---------------- K4: normalize scattered map ---------------------
__global__ void k_normmap()
{
    int p = (blockIdx.x*blockDim.x + threadIdx.x) >> 5;
    int lane = threadIdx.x & 31;
    if (p >= Bsz*HWm) return;
    size_t base = (size_t)p*257;
    float cnt = g_acc[base + 256];
    float msk = (cnt > 0.f) ? 1.f : 0.f;
    float inv = msk / (cnt + 1e-6f);
    for (int c = lane; c < 256; c += 32)
        g_feat[base + c] = g_acc[base + c] * inv;
    if (lane == 0) g_feat[base + 256] = msk;
}

// ---------------- K5: gaussian 3x3 + reconstruct ------------------
__global__ void k_recon()
{
    int pid = blockIdx.x;
    int b  = pid >> 14;
    int yx = pid & 16383;
    int y  = yx >> 7, x = yx & 127;
    int c  = threadIdx.x;

    float e1 = expf(-0.125f), e2 = expf(-0.25f);
    float wsum = 1.f + 4.f*e1 + 4.f*e2;

    size_t pbase = ((size_t)b*HWm + yx)*257;
    float mask_c  = g_feat[pbase + 256];
    float feature = g_feat[pbase + c];
    float filt = 0.f, filtm = 0.f;
#pragma unroll
    for (int dy = -1; dy <= 1; dy++) {
        int ny = y + dy;
        if (ny < 0 || ny >= Hm) continue;
#pragma unroll
        for (int dx = -1; dx <= 1; dx++) {
            int nx = x + dx;
            if (nx < 0 || nx >= Wm) continue;
            int d2 = dy*dy + dx*dx;
            float wgt = ((d2 == 0) ? 1.f : (d2 == 1 ? e1 : e2)) / wsum;
            size_t nb = ((size_t)b*HWm + ny*Wm + nx)*257;
            filt  += wgt * g_feat[nb + c];
            filtm += wgt * g_feat[nb + 256];
        }
    }
    float f_i = filt / (filtm + 1e-6f);
    f_i = (filtm > 0.f) ? f_i : 0.f;
    g_fmap[((size_t)b*HWm + yx)*256 + c] = feature + (1.f - mask_c)*f_i;
}

// ---------------- K6: patch bilinear sample + conv + LN2 ----------
__device__ __forceinline__ float srctap(const float* sp, int xi, int yi, float w)
{
    if (xi < 0 || xi >= Wsrc || yi < 0 || yi >= Hsrc) return 0.f;
    return w * sp[yi*Wsrc + xi];
}

__global__ void k_patch(const float* __restrict__ src, const float* __restrict__ cw,
                        const float* __restrict__ cb,  const float* __restrict__ n2g,
                        const float* __restrict__ n2b)
{
    int tok = blockIdx.x;
    int b = tok >> 14;
    int t = threadIdx.x;
    __shared__ float patch[48];
    __shared__ float red[4];

    float lx = g_loc_extra[2*tok], ly = g_loc_extra[2*tok+1];
    if (t < 48) {
        int c = t >> 4, r = (t >> 2) & 3, col = t & 3;
        float gx = (lx + ((float)col - 1.5f)*(1.f/511.f)) * 512.f - 0.5f;
        float gy = (ly + ((float)r   - 1.5f)*(1.f/511.f)) * 512.f - 0.5f;
        float x0f = floorf(gx), y0f = floorf(gy);
        float wx = gx - x0f, wy = gy - y0f;
        int x0 = (int)x0f, y0 = (int)y0f;
        const float* sp = src + ((size_t)b*3 + c)*Hsrc*Wsrc;
        float v = srctap(sp, x0,   y0,   (1.f-wx)*(1.f-wy))
                + srctap(sp, x0+1, y0,   wx*(1.f-wy))
                + srctap(sp, x0,   y0+1, (1.f-wx)*wy)
                + srctap(sp, x0+1, y0+1, wx*wy);
        patch[t] = v;
    }
    __syncthreads();

    float acc = cb[t];
#pragma unroll
    for (int k = 0; k < 48; k++) acc += patch[k] * cw[t*48 + k];

    float s = acc, sq = acc*acc;
#pragma unroll
    for (int o = 16; o > 0; o >>= 1) { s += __shfl_xor_sync(0xffffffffu, s, o); sq += __shfl_xor_sync(0xffffffffu, sq, o); }
    int wid = t >> 5;
    if ((t & 31) == 0) { red[wid] = s; red[2 + wid] = sq; }
    __syncthreads();
    s  = red[0] + red[1];
    sq = red[2] + red[3];
    float m   = s  * (1.f/64.f);
    float var = sq * (1.f/64.f) - m*m;
    float rr  = rsqrtf(var + 1e-5f);
    float v = (acc - m)*rr*n2g[t] + n2b[t];
    __half h, l; split_h16(v, h, l);
    g_cat_hi[(size_t)tok*CATD + 256 + t] = h;
    g_cat_lo[(size_t)tok*CATD + 256 + t] = l;
}

// ---------------- K7: bilinear gather from fmap -> cat hi/lo ------
__global__ void k_gather()
{
    int tok = (blockIdx.x*blockDim.x + threadIdx.x) >> 5;
    int lane = threadIdx.x & 31;
    if (tok >= Bsz*Ntok) return;
    int b = tok >> 14;
    float gx = g_loc_extra[2*tok]   * 128.f - 0.5f;
    float gy = g_loc_extra[2*tok+1] * 128.f - 0.5f;
    float x0f = floorf(gx), y0f = floorf(gy);
    float wx = gx - x0f, wy = gy - y0f;
    int x0 = (int)x0f, y0 = (int)y0f;
    int x1 = x0 + 1,   y1 = y0 + 1;
    float vx0 = (x0 >= 0 && x0 < Wm) ? 1.f : 0.f;
    float vx1 = (x1 >= 0 && x1 < Wm) ? 1.f : 0.f;
    float vy0 = (y0 >= 0 && y0 < Hm) ? 1.f : 0.f;
    float vy1 = (y1 >= 0 && y1 < Hm) ? 1.f : 0.f;
    float w00 = (1.f-wx)*(1.f-wy)*vx0*vy0;
    float w10 = wx*(1.f-wy)*vx1*vy0;
    float w01 = (1.f-wx)*wy*vx0*vy1;
    float w11 = wx*wy*vx1*vy1;
    int cx0 = min(max(x0,0),Wm-1), cx1 = min(max(x1,0),Wm-1);
    int cy0 = min(max(y0,0),Hm-1), cy1 = min(max(y1,0),Hm-1);
    const float* base = g_fmap + (size_t)b*HWm*256;
    const float* p00 = base + (size_t)(cy0*Wm + cx0)*256;
    const float* p10 = base + (size_t)(cy0*Wm + cx1)*256;
    const float* p01 = base + (size_t)(cy1*Wm + cx0)*256;
    const float* p11 = base + (size_t)(cy1*Wm + cx1)*256;
    size_t obase = (size_t)tok*CATD;
#pragma unroll
    for (int k = 0; k < 8; k++) {
        int c = lane + 32*k;
        float v = w00*p00[c] + w10*p10[c] + w01*p01[c] + w11*p11[c];
        __half h, l; split_h16(v, h, l);
        g_cat_hi[obase + c] = h;
        g_cat_lo[obase + c] = l;
    }
}

// ---------------- weight transpose + fp16: [K][N] -> [N][K] -------
__global__ void k_wsplit(const float* __restrict__ in, int K, int N, int which)
{
    __half* oh = which ? g_w2 : g_w1;
    __shared__ float t[32][33];
    int k0 = blockIdx.y*32, n0 = blockIdx.x*32;
    int x = threadIdx.x, y = threadIdx.y;
#pragma unroll
    for (int i = 0; i < 32; i += 8)
        t[y+i][x] = in[(size_t)(k0+y+i)*N + n0 + x];
    __syncthreads();
#pragma unroll
    for (int i = 0; i < 32; i += 8)
        oh[(size_t)(n0+y+i)*K + k0 + x] = __float2half_rn(t[x][y+i]);
}

// ---------------- HMMA fp16 2-term GEMM (128x128 CTA, K-chunk 32) --
// epi==0: gelu(cat @ w1^T + b1) -> hid_hi/lo fp16     (K=320,  Nn=1024)
// epi==1:       hid @ w2^T + b2 -> out (row-remapped) (K=1024, Nn=256)
// SMEM stage: Ah|Al|B, each 128 rows x 32 fp16, row stride 80B (10240B each).
#define STG   30720
#define NSTG  3
#define GEMM_SMEM (NSTG*STG)

__global__ __launch_bounds__(256) void mma_gemm(const float* __restrict__ bias,
                                                float* __restrict__ outp,
                                                int K, int Nn, int epi)
{
    extern __shared__ char smem[];
    uint32_t sb = smem_u32(smem);

    const __half *Ah, *Al, *Bw;
    if (epi == 0) { Ah = g_cat_hi; Al = g_cat_lo; Bw = g_w1; }
    else          { Ah = g_hid_hi; Al = g_hid_lo; Bw = g_w2; }

    int tid = threadIdx.x, lane = tid & 31, wid = tid >> 5;
    int warpM = wid & 1, warpN = wid >> 1;
    int bm = blockIdx.y*128, bn = blockIdx.x*128;
    int nch = K >> 5;

    const __half* Abase  = Ah + (size_t)bm*K;
    const __half* Albase = Al + (size_t)bm*K;
    const __half* Bbase  = Bw + (size_t)bn*K;

    float acc[4][4][4];
#pragma unroll
    for (int a = 0; a < 4; a++)
#pragma unroll
        for (int b = 0; b < 4; b++)
#pragma unroll
            for (int c = 0; c < 4; c++) acc[a][b][c] = 0.f;

    // ---- async chunk loader (6x cp.async 16B per thread) ----
#define LOAD_CHUNK(i) do { \
    int _k0 = (i) << 5; \
    uint32_t _st = sb + ((i) % NSTG) * STG; \
    _Pragma("unroll") \
    for (int _j = 0; _j < 2; _j++) { \
        int _u = tid + _j*256; \
        int _r = _u >> 2, _kb = _u & 3; \
        size_t _go = (size_t)_r*K + _k0 + _kb*8; \
        uint32_t _do_ = (uint32_t)(_r*80 + _kb*16); \
        CP16(_st + _do_,          Abase  + _go); \
        CP16(_st + 10240 + _do_,  Albase + _go); \
        CP16(_st + 20480 + _do_,  Bbase  + _go); \
    } \
} while (0)

    // prologue: 2 chunks in flight
    LOAD_CHUNK(0); CP_COMMIT();
    if (nch > 1) LOAD_CHUNK(1);
    CP_COMMIT();

    // ldmatrix address components
    int arow = warpM*64 + (lane & 7) + ((lane >> 3) & 1)*8;   // + mf*16
    uint32_t akb = ((lane >> 4) & 1)*16;                      // + kstep*32
    // B x4: groups g=lane>>3: m0={np rows,k0} m1={np,k8} m2={np+8,k0} m3={np+8,k8}
    int brow = warpN*32 + ((lane >> 4) & 1)*8 + (lane & 7);   // + npair*16
    uint32_t bkb = ((lane >> 3) & 1)*16;

    for (int i = 0; i < nch; i++) {
        CP_WAIT1();
        __syncthreads();
        if (i + 2 < nch) LOAD_CHUNK(i + 2);
        CP_COMMIT();

        uint32_t st = sb + (i % NSTG)*STG;
#pragma unroll
        for (int ks = 0; ks < 2; ks++) {
            uint32_t kB = ks*32;
            uint32_t a4[4][4], l4[4][4], bfr[2][4];
#pragma unroll
            for (int mf = 0; mf < 4; mf++) {
                ldsm4(a4[mf], st +         (uint32_t)(arow + mf*16)*80 + akb + kB);
                ldsm4(l4[mf], st + 10240 + (uint32_t)(arow + mf*16)*80 + akb + kB);
            }
#pragma unroll
            for (int np = 0; np < 2; np++)
                ldsm4(bfr[np], st + 20480 + (uint32_t)(brow + np*16)*80 + bkb + kB);
#pragma unroll
            for (int mf = 0; mf < 4; mf++)
#pragma unroll
                for (int nf = 0; nf < 4; nf++) {
                    const uint32_t* bp = &bfr[nf >> 1][(nf & 1)*2];
                    mma16816(acc[mf][nf], a4[mf], bp);
                    mma16816(acc[mf][nf], l4[mf], bp);
                }
        }
    }

    // ---- epilogue ----
    int r0 = bm + warpM*64 + (lane >> 2);
    int cbase = bn + warpN*32 + (lane & 3)*2;
#pragma unroll
    for (int mf = 0; mf < 4; mf++) {
        int row0 = r0 + mf*16;
        int row1 = row0 + 8;
#pragma unroll
        for (int nf = 0; nf < 4; nf++) {
            int col = cbase + nf*8;
            float b0 = bias[col], b1 = bias[col + 1];
            float v00 = acc[mf][nf][0] + b0;
            float v01 = acc[mf][nf][1] + b1;
            float v10 = acc[mf][nf][2] + b0;
            float v11 = acc[mf][nf][3] + b1;
            if (epi == 0) {
                v00 = 0.5f*v00*(1.f + erff(v00*0.70710678118654752f));
                v01 = 0.5f*v01*(1.f + erff(v01*0.70710678118654752f));
                v10 = 0.5f*v10*(1.f + erff(v10*0.70710678118654752f));
                v11 = 0.5f*v11*(1.f + erff(v11*0.70710678118654752f));
                __half h0,l0,h1,l1;
                split_h16(v00,h0,l0); split_h16(v01,h1,l1);
                *(__half2*)(g_hid_hi + (size_t)row0*HIDD + col) = __half2(h0,h1);
                *(__half2*)(g_hid_lo + (size_t)row0*HIDD + col) = __half2(l0,l1);
                split_h16(v10,h0,l0); split_h16(v11,h1,l1);
                *(__half2*)(g_hid_hi + (size_t)row1*HIDD + col) = __half2(h0,h1);
                *(__half2*)(g_hid_lo + (size_t)row1*HIDD + col) = __half2(l0,l1);
            } else {
                int bb0 = row0 >> 14, n0 = row0 & 16383;
                int bb1 = row1 >> 14, n1 = row1 & 16383;
                size_t ob0 = (((size_t)bb0*2*Ntok) + Ntok + n0)*256;
                size_t ob1 = (((size_t)bb1*2*Ntok) + Ntok + n1)*256;
                *(float2*)(outp + ob0 + col) = make_float2(v00, v01);
                *(float2*)(outp + ob1 + col) = make_float2(v10, v11);
            }
        }
    }
}

// ---------------- launch -------------------------------------------
extern "C" void kernel_launch(void* const* d_in, const int* in_sizes, int n_in,
                              void* d_out, int out_size)
{
    (void)in_sizes; (void)n_in; (void)out_size;
    const float* x      = (const float*)d_in[0];
    const float* loc    = (const float*)d_in[1];
    const float* src    = (const float*)d_in[2];
    const float* w_delta = (const float*)d_in[7];
    const float* b_delta = (const float*)d_in[8];
    const float* n1g    = (const float*)d_in[9];
    const float* n1b    = (const float*)d_in[10];
    const float* conv_w = (const float*)d_in[11];
    const float* conv_b = (const float*)d_in[12];
    const float* n2g    = (const float*)d_in[13];
    const float* n2b    = (const float*)d_in[14];
    const float* fc1w   = (const float*)d_in[15];
    const float* fc1b   = (const float*)d_in[16];
    const float* fc2w   = (const float*)d_in[17];
    const float* fc2b   = (const float*)d_in[18];
    float* out = (float*)d_out;
    float* out_loc = out + (size_t)Bsz*2*Ntok*Dm;

    cudaFuncSetAttribute(mma_gemm, cudaFuncAttributeMaxDynamicSharedMemorySize, GEMM_SMEM);

    // weight transpose + fp16 (independent of data path)
    k_wsplit<<<dim3(HIDD/32, CATD/32), dim3(32,8)>>>(fc1w, CATD, HIDD, 0);
    k_wsplit<<<dim3(Dm/32,  HIDD/32), dim3(32,8)>>>(fc2w, HIDD, Dm, 1);

    // zero scatter accumulator
    {
        size_t n4 = (size_t)Bsz*HWm*257/4;
        k_zero_acc<<<(unsigned)((n4 + 255)/256), 256>>>();
    }
    k_delta<<<Bsz*Ntok/8, 256>>>(x, loc, w_delta, b_delta, n1g, n1b, out_loc);
    {
        size_t n4 = (size_t)Bsz*Ntok*Dm/4;
        k_copyx<<<(unsigned)((n4 + 255)/256), 256>>>((const float4*)x, (float4*)out);
    }
    k_scatter<<<Bsz*Ntok/8, 256>>>(x, loc);
    k_normmap<<<Bsz*HWm/8, 256>>>();
    k_recon<<<Bsz*HWm, 256>>>();
    k_patch<<<Bsz*Ntok, 64>>>(src, conv_w, conv_b, n2g, n2b);
    k_gather<<<Bsz*Ntok/8, 256>>>();

    // MLP on tensor cores (fp16 2-term A-split, fp32 accumulate)
    mma_gemm<<<dim3(HIDD/128, Mrows/128), 256, GEMM_SMEM>>>(fc1b, nullptr, CATD, HIDD, 0);
    mma_gemm<<<dim3(Dm/128,   Mrows/128), 256, GEMM_SMEM>>>(fc2b, out,     HIDD, Dm,   1);
}

// round 5
// speedup vs baseline: 2.4255x; 1.2074x over previous
#include <cuda_runtime.h>
#include <cuda_fp16.h>
#include <math.h>
#include <stdint.h>

// ---------------- problem constants (fixed shapes) ----------------
#define Bsz   4
#define Ntok  16384
#define Dm    256
#define LDm   64
#define Hm    128
#define Wm    128
#define HWm   (Hm*Wm)
#define Hsrc  512
#define Wsrc  512
#define CATD  320
#define HIDD  1024
#define Mrows (Bsz*Ntok)

// ---------------- scratch (static device globals; no allocs) ------
__device__ __align__(16) float g_loc_extra[Bsz*Ntok*2];
__device__ __align__(16) float g_acc [Bsz*HWm*257];
__device__ __align__(16) float g_feat[Bsz*HWm*257];
__device__ __align__(16) float g_fmap[(size_t)Bsz*HWm*256];
__device__ __align__(16) __half g_cat[(size_t)Mrows*CATD];
__device__ __align__(16) __half g_hid[(size_t)Mrows*HIDD];
__device__ __align__(16) __half g_w1[(size_t)HIDD*CATD];     // fc1_w^T fp16 [N][K]
__device__ __align__(16) __half g_w2[(size_t)Dm*HIDD];       // fc2_w^T fp16 [N][K]

// ================= PTX helpers (base sm_80+ features only) ==========
__device__ __forceinline__ uint32_t smem_u32(const void* p) {
    uint32_t a;
    asm("{ .reg .u64 t; cvta.to.shared.u64 t, %1; cvt.u32.u64 %0, t; }" : "=r"(a) : "l"(p));
    return a;
}
#define CP16(smem, gptr) \
    asm volatile("cp.async.cg.shared.global [%0], [%1], 16;" :: "r"(smem), "l"(gptr) : "memory")
#define CP_COMMIT() asm volatile("cp.async.commit_group;" ::: "memory")
#define CP_WAIT1()  asm volatile("cp.async.wait_group 1;" ::: "memory")

__device__ __forceinline__ void ldsm4(uint32_t* r, uint32_t addr) {
    asm volatile("ldmatrix.sync.aligned.m8n8.x4.shared.b16 {%0,%1,%2,%3}, [%4];"
        : "=r"(r[0]), "=r"(r[1]), "=r"(r[2]), "=r"(r[3]) : "r"(addr));
}
__device__ __forceinline__ void mma16816(float* d, const uint32_t* a, const uint32_t* b) {
    asm volatile("mma.sync.aligned.m16n8k16.row.col.f32.f16.f16.f32 "
        "{%0,%1,%2,%3}, {%4,%5,%6,%7}, {%8,%9}, {%0,%1,%2,%3};"
        : "+f"(d[0]), "+f"(d[1]), "+f"(d[2]), "+f"(d[3])
        : "r"(a[0]), "r"(a[1]), "r"(a[2]), "r"(a[3]), "r"(b[0]), "r"(b[1]));
}

// ---------------- K0: zero the scatter accumulator ----------------
__global__ void k_zero_acc() {
    size_t n4 = (size_t)Bsz*HWm*257/4;
    size_t i = (size_t)blockIdx.x*blockDim.x + threadIdx.x;
    if (i < n4) ((float4*)g_acc)[i] = make_float4(0.f,0.f,0.f,0.f);
}

// ---------------- K1: LN1 + delta + loc_extra + loc outputs -------
__global__ void k_delta(const float* __restrict__ x, const float* __restrict__ loc,
                        const float* __restrict__ wd, const float* __restrict__ bd,
                        const float* __restrict__ n1g, const float* __restrict__ n1b,
                        float* __restrict__ out_loc_base)
{
    int w = (blockIdx.x*blockDim.x + threadIdx.x) >> 5;
    int lane = threadIdx.x & 31;
    if (w >= Bsz*Ntok) return;
    const float* xr = x + (size_t)w*Dm;
    float v[8], s = 0.f, sq = 0.f;
#pragma unroll
    for (int k = 0; k < 8; k++) { v[k] = xr[lane + 32*k]; s += v[k]; sq += v[k]*v[k]; }
#pragma unroll
    for (int o = 16; o > 0; o >>= 1) { s += __shfl_xor_sync(0xffffffffu, s, o); sq += __shfl_xor_sync(0xffffffffu, sq, o); }
    float m   = s  * (1.f/256.f);
    float var = sq * (1.f/256.f) - m*m;
    float r   = rsqrtf(var + 1e-5f);
    float d0 = 0.f, d1 = 0.f;
#pragma unroll
    for (int k = 0; k < 8; k++) {
        int c = lane + 32*k;
        float y = (v[k]-m)*r*n1g[c] + n1b[c];
        d0 += y * wd[2*c];
        d1 += y * wd[2*c+1];
    }
#pragma unroll
    for (int o = 16; o > 0; o >>= 1) { d0 += __shfl_xor_sync(0xffffffffu, d0, o); d1 += __shfl_xor_sync(0xffffffffu, d1, o); }
    if (lane == 0) {
        float l0 = loc[2*w], l1 = loc[2*w+1];
        float e0 = fminf(fmaxf(l0 + (d0 + bd[0])*0.01f, 0.f), 1.f);
        float e1 = fminf(fmaxf(l1 + (d1 + bd[1])*0.01f, 0.f), 1.f);
        g_loc_extra[2*w]   = e0;
        g_loc_extra[2*w+1] = e1;
        int b = w / Ntok, n = w % Ntok;
        float* o1 = out_loc_base + ((size_t)b*2*Ntok + n)*2;
        o1[0] = l0; o1[1] = l1;
        float* o2 = out_loc_base + ((size_t)b*2*Ntok + Ntok + n)*2;
        o2[0] = e0; o2[1] = e1;
    }
}

// ---------------- K2: copy x into first-half tokens of output -----
__global__ void k_copyx(const float4* __restrict__ x, float4* __restrict__ out)
{
    size_t per = (size_t)Ntok*Dm/4;
    size_t i = (size_t)blockIdx.x*blockDim.x + threadIdx.x;
    if (i >= (size_t)Bsz*per) return;
    size_t b = i / per, rem = i % per;
    out[b*2*per + rem] = x[i];
}

// ---------------- K3: token2map scatter-add -----------------------
__global__ void k_scatter(const float* __restrict__ x, const float* __restrict__ loc)
{
    int w = (blockIdx.x*blockDim.x + threadIdx.x) >> 5;
    int lane = threadIdx.x & 31;
    if (w >= Bsz*Ntok) return;
    int b = w / Ntok;
    float lx = fminf(fmaxf(loc[2*w],   0.f), 1.f) * (float)(Wm-1);
    float ly = fminf(fmaxf(loc[2*w+1], 0.f), 1.f) * (float)(Hm-1);
    int xi = (int)rintf(lx);
    int yi = (int)rintf(ly);
    size_t base = ((size_t)b*HWm + yi*Wm + xi) * 257;
    const float* xr = x + (size_t)w*Dm;
    for (int c = lane; c < 257; c += 32) {
        float val = (c < 256) ? xr[c] : 1.f;
        atomicAdd(&g_acc[base + c], val);
    }
}

// ---------------- K4: normalize scattered map ---------------------
__global__ void k_normmap()
{
    int p = (blockIdx.x*blockDim.x + threadIdx.x) >> 5;
    int lane = threadIdx.x & 31;
    if (p >= Bsz*HWm) return;
    size_t base = (size_t)p*257;
    float cnt = g_acc[base + 256];
    float msk = (cnt > 0.f) ? 1.f : 0.f;
    float inv = msk / (cnt + 1e-6f);
    for (int c = lane; c < 256; c += 32)
        g_feat[base + c] = g_acc[base + c] * inv;
    if (lane == 0) g_feat[base + 256] = msk;
}

// ---------------- K5: gaussian 3x3 + reconstruct ------------------
__global__ void k_recon()
{
    int pid = blockIdx.x;
    int b  = pid >> 14;
    int yx = pid & 16383;
    int y  = yx >> 7, x = yx & 127;
    int c  = threadIdx.x;

    float e1 = expf(-0.125f), e2 = expf(-0.25f);
    float wsum = 1.f + 4.f*e1 + 4.f*e2;

    size_t pbase = ((size_t)b*HWm + yx)*257;
    float mask_c  = g_feat[pbase + 256];
    float feature = g_feat[pbase + c];
    float filt = 0.f, filtm = 0.f;
#pragma unroll
    for (int dy = -1; dy <= 1; dy++) {
        int ny = y + dy;
        if (ny < 0 || ny >= Hm) continue;
#pragma unroll
        for (int dx = -1; dx <= 1; dx++) {
            int nx = x + dx;
            if (nx < 0 || nx >= Wm) continue;
            int d2 = dy*dy + dx*dx;
            float wgt = ((d2 == 0) ? 1.f : (d2 == 1 ? e1 : e2)) / wsum;
            size_t nb = ((size_t)b*HWm + ny*Wm + nx)*257;
            filt  += wgt * g_feat[nb + c];
            filtm += wgt * g_feat[nb + 256];
        }
    }
    float f_i = filt / (filtm + 1e-6f);
    f_i = (filtm > 0.f) ? f_i : 0.f;
    g_fmap[((size_t)b*HWm + yx)*256 + c] = feature + (1.f - mask_c)*f_i;
}

// ---------------- K6: patch bilinear sample + conv + LN2 ----------
__device__ __forceinline__ float srctap(const float* sp, int xi, int yi, float w)
{
    if (xi < 0 || xi >= Wsrc || yi < 0 || yi >= Hsrc) return 0.f;
    return w * sp[yi*Wsrc + xi];
}

__global__ void k_patch(const float* __restrict__ src, const float* __restrict__ cw,
                        const float* __restrict__ cb,  const float* __restrict__ n2g,
                        const float* __restrict__ n2b)
{
    int tok = blockIdx.x;
    int b = tok >> 14;
    int t = threadIdx.x;
    __shared__ float patch[48];
    __shared__ float red[4];

    float lx = g_loc_extra[2*tok], ly = g_loc_extra[2*tok+1];
    if (t < 48) {
        int c = t >> 4, r = (t >> 2) & 3, col = t & 3;
        float gx = (lx + ((float)col - 1.5f)*(1.f/511.f)) * 512.f - 0.5f;
        float gy = (ly + ((float)r   - 1.5f)*(1.f/511.f)) * 512.f - 0.5f;
        float x0f = floorf(gx), y0f = floorf(gy);
        float wx = gx - x0f, wy = gy - y0f;
        int x0 = (int)x0f, y0 = (int)y0f;
        const float* sp = src + ((size_t)b*3 + c)*Hsrc*Wsrc;
        float v = srctap(sp, x0,   y0,   (1.f-wx)*(1.f-wy))
                + srctap(sp, x0+1, y0,   wx*(1.f-wy))
                + srctap(sp, x0,   y0+1, (1.f-wx)*wy)
                + srctap(sp, x0+1, y0+1, wx*wy);
        patch[t] = v;
    }
    __syncthreads();

    float acc = cb[t];
#pragma unroll
    for (int k = 0; k < 48; k++) acc += patch[k] * cw[t*48 + k];

    float s = acc, sq = acc*acc;
#pragma unroll
    for (int o = 16; o > 0; o >>= 1) { s += __shfl_xor_sync(0xffffffffu, s, o); sq += __shfl_xor_sync(0xffffffffu, sq, o); }
    int wid = t >> 5;
    if ((t & 31) == 0) { red[wid] = s; red[2 + wid] = sq; }
    __syncthreads();
    s  = red[0] + red[1];
    sq = red[2] + red[3];
    float m   = s  * (1.f/64.f);
    float var = sq * (1.f/64.f) - m*m;
    float rr  = rsqrtf(var + 1e-5f);
    float v = (acc - m)*rr*n2g[t] + n2b[t];
    g_cat[(size_t)tok*CATD + 256 + t] = __float2half_rn(v);
}

// ---------------- K7: bilinear gather from fmap -> cat fp16 -------
__global__ void k_gather()
{
    int tok = (blockIdx.x*blockDim.x + threadIdx.x) >> 5;
    int lane = threadIdx.x & 31;
    if (tok >= Bsz*Ntok) return;
    int b = tok >> 14;
    float gx = g_loc_extra[2*tok]   * 128.f - 0.5f;
    float gy = g_loc_extra[2*tok+1] * 128.f - 0.5f;
    float x0f = floorf(gx), y0f = floorf(gy);
    float wx = gx - x0f, wy = gy - y0f;
    int x0 = (int)x0f, y0 = (int)y0f;
    int x1 = x0 + 1,   y1 = y0 + 1;
    float vx0 = (x0 >= 0 && x0 < Wm) ? 1.f : 0.f;
    float vx1 = (x1 >= 0 && x1 < Wm) ? 1.f : 0.f;
    float vy0 = (y0 >= 0 && y0 < Hm) ? 1.f : 0.f;
    float vy1 = (y1 >= 0 && y1 < Hm) ? 1.f : 0.f;
    float w00 = (1.f-wx)*(1.f-wy)*vx0*vy0;
    float w10 = wx*(1.f-wy)*vx1*vy0;
    float w01 = (1.f-wx)*wy*vx0*vy1;
    float w11 = wx*wy*vx1*vy1;
    int cx0 = min(max(x0,0),Wm-1), cx1 = min(max(x1,0),Wm-1);
    int cy0 = min(max(y0,0),Hm-1), cy1 = min(max(y1,0),Hm-1);
    const float* base = g_fmap + (size_t)b*HWm*256;
    const float* p00 = base + (size_t)(cy0*Wm + cx0)*256;
    const float* p10 = base + (size_t)(cy0*Wm + cx1)*256;
    const float* p01 = base + (size_t)(cy1*Wm + cx0)*256;
    const float* p11 = base + (size_t)(cy1*Wm + cx1)*256;
    size_t obase = (size_t)tok*CATD;
#pragma unroll
    for (int k = 0; k < 8; k++) {
        int c = lane + 32*k;
        float v = w00*p00[c] + w10*p10[c] + w01*p01[c] + w11*p11[c];
        g_cat[obase + c] = __float2half_rn(v);
    }
}

// ---------------- weight transpose + fp16: [K][N] -> [N][K] -------
__global__ void k_wsplit(const float* __restrict__ in, int K, int N, int which)
{
    __half* oh = which ? g_w2 : g_w1;
    __shared__ float t[32][33];
    int k0 = blockIdx.y*32, n0 = blockIdx.x*32;
    int x = threadIdx.x, y = threadIdx.y;
#pragma unroll
    for (int i = 0; i < 32; i += 8)
        t[y+i][x] = in[(size_t)(k0+y+i)*N + n0 + x];
    __syncthreads();
#pragma unroll
    for (int i = 0; i < 32; i += 8)
        oh[(size_t)(n0+y+i)*K + k0 + x] = __float2half_rn(t[x][y+i]);
}

// ---------------- HMMA fp16 GEMM (128x128 CTA, K-chunk 32) --------
// epi==0: gelu(cat @ w1^T + b1) -> hid fp16           (K=320,  Nn=1024)
// epi==1:       hid @ w2^T + b2 -> out (row-remapped) (K=1024, Nn=256)
// SMEM stage: A|B, each 128 rows x 32 fp16, row stride 80B (10240B each).
#define STG   20480
#define NSTG  3
#define GEMM_SMEM (NSTG*STG)

__global__ __launch_bounds__(256) void mma_gemm(const float* __restrict__ bias,
                                                float* __restrict__ outp,
                                                int K, int Nn, int epi)
{
    extern __shared__ char smem[];
    uint32_t sb = smem_u32(smem);

    const __half *Ah, *Bw;
    if (epi == 0) { Ah = g_cat; Bw = g_w1; }
    else          { Ah = g_hid; Bw = g_w2; }

    int tid = threadIdx.x, lane = tid & 31, wid = tid >> 5;
    int warpM = wid & 1, warpN = wid >> 1;
    int bm = blockIdx.y*128, bn = blockIdx.x*128;
    int nch = K >> 5;

    const __half* Abase = Ah + (size_t)bm*K;
    const __half* Bbase = Bw + (size_t)bn*K;

    float acc[4][4][4];
#pragma unroll
    for (int a = 0; a < 4; a++)
#pragma unroll
        for (int b = 0; b < 4; b++)
#pragma unroll
            for (int c = 0; c < 4; c++) acc[a][b][c] = 0.f;

    // ---- async chunk loader (4x cp.async 16B per thread) ----
#define LOAD_CHUNK(i) do { \
    int _k0 = (i) << 5; \
    uint32_t _st = sb + ((i) % NSTG) * STG; \
    _Pragma("unroll") \
    for (int _j = 0; _j < 2; _j++) { \
        int _u = tid + _j*256; \
        int _r = _u >> 2, _kb = _u & 3; \
        size_t _go = (size_t)_r*K + _k0 + _kb*8; \
        uint32_t _do_ = (uint32_t)(_r*80 + _kb*16); \
        CP16(_st + _do_,          Abase + _go); \
        CP16(_st + 10240 + _do_,  Bbase + _go); \
    } \
} while (0)

    // prologue: 2 chunks in flight
    LOAD_CHUNK(0); CP_COMMIT();
    if (nch > 1) LOAD_CHUNK(1);
    CP_COMMIT();

    // ldmatrix address components
    int arow = warpM*64 + (lane & 7) + ((lane >> 3) & 1)*8;   // + mf*16
    uint32_t akb = ((lane >> 4) & 1)*16;                      // + kstep*32
    int brow = warpN*32 + ((lane >> 4) & 1)*8 + (lane & 7);   // + npair*16
    uint32_t bkb = ((lane >> 3) & 1)*16;

    for (int i = 0; i < nch; i++) {
        CP_WAIT1();
        __syncthreads();
        if (i + 2 < nch) LOAD_CHUNK(i + 2);
        CP_COMMIT();

        uint32_t st = sb + (i % NSTG)*STG;
#pragma unroll
        for (int ks = 0; ks < 2; ks++) {
            uint32_t kB = ks*32;
            uint32_t a4[4][4], bfr[2][4];
#pragma unroll
            for (int mf = 0; mf < 4; mf++)
                ldsm4(a4[mf], st + (uint32_t)(arow + mf*16)*80 + akb + kB);
#pragma unroll
            for (int np = 0; np < 2; np++)
                ldsm4(bfr[np], st + 10240 + (uint32_t)(brow + np*16)*80 + bkb + kB);
#pragma unroll
            for (int mf = 0; mf < 4; mf++)
#pragma unroll
                for (int nf = 0; nf < 4; nf++) {
                    const uint32_t* bp = &bfr[nf >> 1][(nf & 1)*2];
                    mma16816(acc[mf][nf], a4[mf], bp);
                }
        }
    }

    // ---- epilogue ----
    int r0 = bm + warpM*64 + (lane >> 2);
    int cbase = bn + warpN*32 + (lane & 3)*2;
#pragma unroll
    for (int mf = 0; mf < 4; mf++) {
        int row0 = r0 + mf*16;
        int row1 = row0 + 8;
#pragma unroll
        for (int nf = 0; nf < 4; nf++) {
            int col = cbase + nf*8;
            float b0 = bias[col], b1 = bias[col + 1];
            float v00 = acc[mf][nf][0] + b0;
            float v01 = acc[mf][nf][1] + b1;
            float v10 = acc[mf][nf][2] + b0;
            float v11 = acc[mf][nf][3] + b1;
            if (epi == 0) {
                v00 = 0.5f*v00*(1.f + erff(v00*0.70710678118654752f));
                v01 = 0.5f*v01*(1.f + erff(v01*0.70710678118654752f));
                v10 = 0.5f*v10*(1.f + erff(v10*0.70710678118654752f));
                v11 = 0.5f*v11*(1.f + erff(v11*0.70710678118654752f));
                *(__half2*)(g_hid + (size_t)row0*HIDD + col) =
                    __half2(__float2half_rn(v00), __float2half_rn(v01));
                *(__half2*)(g_hid + (size_t)row1*HIDD + col) =
                    __half2(__float2half_rn(v10), __float2half_rn(v11));
            } else {
                int bb0 = row0 >> 14, n0 = row0 & 16383;
                int bb1 = row1 >> 14, n1 = row1 & 16383;
                size_t ob0 = (((size_t)bb0*2*Ntok) + Ntok + n0)*256;
                size_t ob1 = (((size_t)bb1*2*Ntok) + Ntok + n1)*256;
                *(float2*)(outp + ob0 + col) = make_float2(v00, v01);
                *(float2*)(outp + ob1 + col) = make_float2(v10, v11);
            }
        }
    }
}

// ---------------- launch -------------------------------------------
extern "C" void kernel_launch(void* const* d_in, const int* in_sizes, int n_in,
                              void* d_out, int out_size)
{
    (void)in_sizes; (void)n_in; (void)out_size;
    const float* x      = (const float*)d_in[0];
    const float* loc    = (const float*)d_in[1];
    const float* src    = (const float*)d_in[2];
    const float* w_delta = (const float*)d_in[7];
    const float* b_delta = (const float*)d_in[8];
    const float* n1g    = (const float*)d_in[9];
    const float* n1b    = (const float*)d_in[10];
    const float* conv_w = (const float*)d_in[11];
    const float* conv_b = (const float*)d_in[12];
    const float* n2g    = (const float*)d_in[13];
    const float* n2b    = (const float*)d_in[14];
    const float* fc1w   = (const float*)d_in[15];
    const float* fc1b   = (const float*)d_in[16];
    const float* fc2w   = (const float*)d_in[17];
    const float* fc2b   = (const float*)d_in[18];
    float* out = (float*)d_out;
    float* out_loc = out + (size_t)Bsz*2*Ntok*Dm;

    cudaFuncSetAttribute(mma_gemm, cudaFuncAttributeMaxDynamicSharedMemorySize, GEMM_SMEM);

    // weight transpose + fp16 (independent of data path)
    k_wsplit<<<dim3(HIDD/32, CATD/32), dim3(32,8)>>>(fc1w, CATD, HIDD, 0);
    k_wsplit<<<dim3(Dm/32,  HIDD/32), dim3(32,8)>>>(fc2w, HIDD, Dm, 1);

    // zero scatter accumulator
    {
        size_t n4 = (size_t)Bsz*HWm*257/4;
        k_zero_acc<<<(unsigned)((n4 + 255)/256), 256>>>();
    }
    k_delta<<<Bsz*Ntok/8, 256>>>(x, loc, w_delta, b_delta, n1g, n1b, out_loc);
    {
        size_t n4 = (size_t)Bsz*Ntok*Dm/4;
        k_copyx<<<(unsigned)((n4 + 255)/256), 256>>>((const float4*)x, (float4*)out);
    }
    k_scatter<<<Bsz*Ntok/8, 256>>>(x, loc);
    k_normmap<<<Bsz*HWm/8, 256>>>();
    k_recon<<<Bsz*HWm, 256>>>();
    k_patch<<<Bsz*Ntok, 64>>>(src, conv_w, conv_b, n2g, n2b);
    k_gather<<<Bsz*Ntok/8, 256>>>();

    // MLP on tensor cores (fp16 single-term, fp32 accumulate)
    mma_gemm<<<dim3(HIDD/128, Mrows/128), 256, GEMM_SMEM>>>(fc1b, nullptr, CATD, HIDD, 0);
    mma_gemm<<<dim3(Dm/128,   Mrows/128), 256, GEMM_SMEM>>>(fc2b, out,     HIDD, Dm,   1);
}

// round 6
// speedup vs baseline: 4.3970x; 1.8128x over previous
#include <cuda_runtime.h>
#include <cuda_fp16.h>
#include <math.h>
#include <stdint.h>

// ---------------- problem constants (fixed shapes) ----------------
#define Bsz   4
#define Ntok  16384
#define Dm    256
#define LDm   64
#define Hm    128
#define Wm    128
#define HWm   (Hm*Wm)
#define Hsrc  512
#define Wsrc  512
#define CATD  320
#define HIDD  1024
#define Mrows (Bsz*Ntok)

// ---------------- scratch (static device globals; no allocs) ------
__device__ __align__(16) float g_loc_extra[Bsz*Ntok*2];
__device__ __align__(16) float g_acc [Bsz*HWm*257];
__device__ __align__(16) float g_fmap[(size_t)Bsz*HWm*256];
__device__ __align__(16) __half g_cat[(size_t)Mrows*CATD];
__device__ __align__(16) __half g_hid[(size_t)Mrows*HIDD];
__device__ __align__(16) __half g_w1[(size_t)HIDD*CATD];     // fc1_w^T fp16 [N][K]
__device__ __align__(16) __half g_w2[(size_t)Dm*HIDD];       // fc2_w^T fp16 [N][K]

// ================= PTX helpers (base sm_80+ features only) ==========
__device__ __forceinline__ uint32_t smem_u32(const void* p) {
    uint32_t a;
    asm("{ .reg .u64 t; cvta.to.shared.u64 t, %1; cvt.u32.u64 %0, t; }" : "=r"(a) : "l"(p));
    return a;
}
#define CP16(smem, gptr) \
    asm volatile("cp.async.cg.shared.global [%0], [%1], 16;" :: "r"(smem), "l"(gptr) : "memory")
#define CP_COMMIT() asm volatile("cp.async.commit_group;" ::: "memory")
#define CP_WAIT1()  asm volatile("cp.async.wait_group 1;" ::: "memory")

__device__ __forceinline__ void ldsm4(uint32_t* r, uint32_t addr) {
    asm volatile("ldmatrix.sync.aligned.m8n8.x4.shared.b16 {%0,%1,%2,%3}, [%4];"
        : "=r"(r[0]), "=r"(r[1]), "=r"(r[2]), "=r"(r[3]) : "r"(addr));
}
__device__ __forceinline__ void mma16816(float* d, const uint32_t* a, const uint32_t* b) {
    asm volatile("mma.sync.aligned.m16n8k16.row.col.f32.f16.f16.f32 "
        "{%0,%1,%2,%3}, {%4,%5,%6,%7}, {%8,%9}, {%0,%1,%2,%3};"
        : "+f"(d[0]), "+f"(d[1]), "+f"(d[2]), "+f"(d[3])
        : "r"(a[0]), "r"(a[1]), "r"(a[2]), "r"(a[3]), "r"(b[0]), "r"(b[1]));
}

// ---------------- K0: zero the scatter accumulator ----------------
__global__ void k_zero_acc() {
    size_t n4 = (size_t)Bsz*HWm*257/4;
    size_t i = (size_t)blockIdx.x*blockDim.x + threadIdx.x;
    if (i < n4) ((float4*)g_acc)[i] = make_float4(0.f,0.f,0.f,0.f);
}

// ---------------- K1: LN1 + delta + loc_extra + loc outputs -------
__global__ void k_delta(const float* __restrict__ x, const float* __restrict__ loc,
                        const float* __restrict__ wd, const float* __restrict__ bd,
                        const float* __restrict__ n1g, const float* __restrict__ n1b,
                        float* __restrict__ out_loc_base)
{
    int w = (blockIdx.x*blockDim.x + threadIdx.x) >> 5;
    int lane = threadIdx.x & 31;
    if (w >= Bsz*Ntok) return;
    const float* xr = x + (size_t)w*Dm;
    float v[8], s = 0.f, sq = 0.f;
#pragma unroll
    for (int k = 0; k < 8; k++) { v[k] = xr[lane + 32*k]; s += v[k]; sq += v[k]*v[k]; }
#pragma unroll
    for (int o = 16; o > 0; o >>= 1) { s += __shfl_xor_sync(0xffffffffu, s, o); sq += __shfl_xor_sync(0xffffffffu, sq, o); }
    float m   = s  * (1.f/256.f);
    float var = sq * (1.f/256.f) - m*m;
    float r   = rsqrtf(var + 1e-5f);
    float d0 = 0.f, d1 = 0.f;
#pragma unroll
    for (int k = 0; k < 8; k++) {
        int c = lane + 32*k;
        float y = (v[k]-m)*r*n1g[c] + n1b[c];
        d0 += y * wd[2*c];
        d1 += y * wd[2*c+1];
    }
#pragma unroll
    for (int o = 16; o > 0; o >>= 1) { d0 += __shfl_xor_sync(0xffffffffu, d0, o); d1 += __shfl_xor_sync(0xffffffffu, d1, o); }
    if (lane == 0) {
        float l0 = loc[2*w], l1 = loc[2*w+1];
        float e0 = fminf(fmaxf(l0 + (d0 + bd[0])*0.01f, 0.f), 1.f);
        float e1 = fminf(fmaxf(l1 + (d1 + bd[1])*0.01f, 0.f), 1.f);
        g_loc_extra[2*w]   = e0;
        g_loc_extra[2*w+1] = e1;
        int b = w / Ntok, n = w % Ntok;
        float* o1 = out_loc_base + ((size_t)b*2*Ntok + n)*2;
        o1[0] = l0; o1[1] = l1;
        float* o2 = out_loc_base + ((size_t)b*2*Ntok + Ntok + n)*2;
        o2[0] = e0; o2[1] = e1;
    }
}

// ---------------- K2: copy x into first-half tokens of output -----
__global__ void k_copyx(const float4* __restrict__ x, float4* __restrict__ out)
{
    size_t per = (size_t)Ntok*Dm/4;
    size_t i = (size_t)blockIdx.x*blockDim.x + threadIdx.x;
    if (i >= (size_t)Bsz*per) return;
    size_t b = i / per, rem = i % per;
    out[b*2*per + rem] = x[i];
}

// ---------------- K3: token2map scatter-add -----------------------
__global__ void k_scatter(const float* __restrict__ x, const float* __restrict__ loc)
{
    int w = (blockIdx.x*blockDim.x + threadIdx.x) >> 5;
    int lane = threadIdx.x & 31;
    if (w >= Bsz*Ntok) return;
    int b = w / Ntok;
    float lx = fminf(fmaxf(loc[2*w],   0.f), 1.f) * (float)(Wm-1);
    float ly = fminf(fmaxf(loc[2*w+1], 0.f), 1.f) * (float)(Hm-1);
    int xi = (int)rintf(lx);
    int yi = (int)rintf(ly);
    size_t base = ((size_t)b*HWm + yi*Wm + xi) * 257;
    const float* xr = x + (size_t)w*Dm;
    for (int c = lane; c < 257; c += 32) {
        float val = (c < 256) ? xr[c] : 1.f;
        atomicAdd(&g_acc[base + c], val);
    }
}

// ---------------- K5: fused normalize + gaussian 3x3 + reconstruct
// One block handles 8 consecutive x-pixels; thread = channel.
__global__ void k_recon()
{
    int pid8 = blockIdx.x;                 // 0 .. B*HW/8-1
    int b    = pid8 >> 11;                 // HW/8 = 2048
    int rem  = pid8 & 2047;
    int y    = rem >> 4;                   // 16 blocks per row
    int x0   = (rem & 15) << 3;
    int c    = threadIdx.x;                // 0..255

    __shared__ float s_inv[3][10];
    __shared__ float s_msk[3][10];

    if (c < 30) {
        int r = c / 10, cc = c % 10;
        int ny = y - 1 + r, nx = x0 - 1 + cc;
        bool valid = (ny >= 0 && ny < Hm && nx >= 0 && nx < Wm);
        float cnt = valid ? g_acc[((size_t)b*HWm + ny*Wm + nx)*257 + 256] : 0.f;
        float msk = (valid && cnt > 0.f) ? 1.f : 0.f;
        s_msk[r][cc] = msk;
        s_inv[r][cc] = valid ? (msk / (cnt + 1e-6f)) : 0.f;
    }
    __syncthreads();

    float vals[3][10];
#pragma unroll
    for (int r = 0; r < 3; r++) {
        int ny = y - 1 + r;
        bool rok = (ny >= 0 && ny < Hm);
#pragma unroll
        for (int cc = 0; cc < 10; cc++) {
            int nx = x0 - 1 + cc;
            bool valid = rok && (nx >= 0 && nx < Wm);
            float v = valid ? g_acc[((size_t)b*HWm + ny*Wm + nx)*257 + c] : 0.f;
            vals[r][cc] = v * s_inv[r][cc];
        }
    }

    float e1 = expf(-0.125f), e2 = expf(-0.25f);
    float wsum = 1.f + 4.f*e1 + 4.f*e2;
    float w0 = 1.f/wsum, w1 = e1/wsum, w2 = e2/wsum;
    // weight by (|dy|,|dx|): (0,0)->w0 (0,1)/(1,0)->w1 (1,1)->w2
    float wgt[3][3] = {{w2,w1,w2},{w1,w0,w1},{w2,w1,w2}};

#pragma unroll
    for (int i = 0; i < 8; i++) {
        float feature = vals[1][i+1];
        float mask_c  = s_msk[1][i+1];
        float filt = 0.f, filtm = 0.f;
#pragma unroll
        for (int r = 0; r < 3; r++)
#pragma unroll
            for (int dx = 0; dx < 3; dx++) {
                float w = wgt[r][dx];
                filt  += w * vals[r][i+dx];
                filtm += w * s_msk[r][i+dx];
            }
        float f_i = filt / (filtm + 1e-6f);
        f_i = (filtm > 0.f) ? f_i : 0.f;
        g_fmap[((size_t)b*HWm + y*Wm + x0 + i)*256 + c] = feature + (1.f - mask_c)*f_i;
    }
}

// ---------------- K6: patch sample + conv + LN2 (8 tokens/block) --
__device__ __forceinline__ float srctap(const float* sp, int xi, int yi, float w)
{
    if (xi < 0 || xi >= Wsrc || yi < 0 || yi >= Hsrc) return 0.f;
    return w * sp[yi*Wsrc + xi];
}

__global__ __launch_bounds__(512) void k_patch(const float* __restrict__ src,
                        const float* __restrict__ cw,
                        const float* __restrict__ cb,  const float* __restrict__ n2g,
                        const float* __restrict__ n2b)
{
    __shared__ float s_cw[64*49];          // padded stride 49 (conflict-free)
    __shared__ float s_patch[8][48];
    __shared__ float s_red[8][4];

    int tid = threadIdx.x;
    // stage conv weights [64][48] with pad
    for (int i = tid; i < 64*48; i += 512)
        s_cw[(i/48)*49 + (i%48)] = cw[i];

    int sub = tid >> 6;                    // 0..7 token slot
    int t   = tid & 63;
    int tok = blockIdx.x*8 + sub;
    int b   = tok >> 14;

    float lx = g_loc_extra[2*tok], ly = g_loc_extra[2*tok+1];
    if (t < 48) {
        int cch = t >> 4, r = (t >> 2) & 3, col = t & 3;
        float gx = (lx + ((float)col - 1.5f)*(1.f/511.f)) * 512.f - 0.5f;
        float gy = (ly + ((float)r   - 1.5f)*(1.f/511.f)) * 512.f - 0.5f;
        float x0f = floorf(gx), y0f = floorf(gy);
        float wx = gx - x0f, wy = gy - y0f;
        int x0 = (int)x0f, y0 = (int)y0f;
        const float* sp = src + ((size_t)b*3 + cch)*Hsrc*Wsrc;
        float v = srctap(sp, x0,   y0,   (1.f-wx)*(1.f-wy))
                + srctap(sp, x0+1, y0,   wx*(1.f-wy))
                + srctap(sp, x0,   y0+1, (1.f-wx)*wy)
                + srctap(sp, x0+1, y0+1, wx*wy);
        s_patch[sub][t] = v;
    }
    __syncthreads();

    float acc = cb[t];
#pragma unroll
    for (int k = 0; k < 48; k++) acc += s_patch[sub][k] * s_cw[t*49 + k];

    float s = acc, sq = acc*acc;
#pragma unroll
    for (int o = 16; o > 0; o >>= 1) { s += __shfl_xor_sync(0xffffffffu, s, o); sq += __shfl_xor_sync(0xffffffffu, sq, o); }
    int wh = t >> 5;
    if ((t & 31) == 0) { s_red[sub][wh] = s; s_red[sub][2 + wh] = sq; }
    __syncthreads();
    s  = s_red[sub][0] + s_red[sub][1];
    sq = s_red[sub][2] + s_red[sub][3];
    float m   = s  * (1.f/64.f);
    float var = sq * (1.f/64.f) - m*m;
    float rr  = rsqrtf(var + 1e-5f);
    float v = (acc - m)*rr*n2g[t] + n2b[t];
    g_cat[(size_t)tok*CATD + 256 + t] = __float2half_rn(v);
}

// ---------------- K7: bilinear gather from fmap -> cat fp16 -------
__global__ void k_gather()
{
    int tok = (blockIdx.x*blockDim.x + threadIdx.x) >> 5;
    int lane = threadIdx.x & 31;
    if (tok >= Bsz*Ntok) return;
    int b = tok >> 14;
    float gx = g_loc_extra[2*tok]   * 128.f - 0.5f;
    float gy = g_loc_extra[2*tok+1] * 128.f - 0.5f;
    float x0f = floorf(gx), y0f = floorf(gy);
    float wx = gx - x0f, wy = gy - y0f;
    int x0 = (int)x0f, y0 = (int)y0f;
    int x1 = x0 + 1,   y1 = y0 + 1;
    float vx0 = (x0 >= 0 && x0 < Wm) ? 1.f : 0.f;
    float vx1 = (x1 >= 0 && x1 < Wm) ? 1.f : 0.f;
    float vy0 = (y0 >= 0 && y0 < Hm) ? 1.f : 0.f;
    float vy1 = (y1 >= 0 && y1 < Hm) ? 1.f : 0.f;
    float w00 = (1.f-wx)*(1.f-wy)*vx0*vy0;
    float w10 = wx*(1.f-wy)*vx1*vy0;
    float w01 = (1.f-wx)*wy*vx0*vy1;
    float w11 = wx*wy*vx1*vy1;
    int cx0 = min(max(x0,0),Wm-1), cx1 = min(max(x1,0),Wm-1);
    int cy0 = min(max(y0,0),Hm-1), cy1 = min(max(y1,0),Hm-1);
    const float* base = g_fmap + (size_t)b*HWm*256;
    const float* p00 = base + (size_t)(cy0*Wm + cx0)*256;
    const float* p10 = base + (size_t)(cy0*Wm + cx1)*256;
    const float* p01 = base + (size_t)(cy1*Wm + cx0)*256;
    const float* p11 = base + (size_t)(cy1*Wm + cx1)*256;
    size_t obase = (size_t)tok*CATD;
#pragma unroll
    for (int k = 0; k < 8; k++) {
        int c = lane + 32*k;
        float v = w00*p00[c] + w10*p10[c] + w01*p01[c] + w11*p11[c];
        g_cat[obase + c] = __float2half_rn(v);
    }
}

// ---------------- weight transpose + fp16: [K][N] -> [N][K] -------
__global__ void k_wsplit(const float* __restrict__ in, int K, int N, int which)
{
    __half* oh = which ? g_w2 : g_w1;
    __shared__ float t[32][33];
    int k0 = blockIdx.y*32, n0 = blockIdx.x*32;
    int x = threadIdx.x, y = threadIdx.y;
#pragma unroll
    for (int i = 0; i < 32; i += 8)
        t[y+i][x] = in[(size_t)(k0+y+i)*N + n0 + x];
    __syncthreads();
#pragma unroll
    for (int i = 0; i < 32; i += 8)
        oh[(size_t)(n0+y+i)*K + k0 + x] = __float2half_rn(t[x][y+i]);
}

// ---------------- HMMA fp16 GEMM (128x128 CTA, K-chunk 64) --------
// epi==0: gelu(cat @ w1^T + b1) -> hid fp16           (K=320,  Nn=1024)
// epi==1:       hid @ w2^T + b2 -> out (row-remapped) (K=1024, Nn=256)
// SMEM stage: A|B, each 128 rows x 64 fp16, row stride 144B (18432B each).
#define STG   36864
#define NSTG  3
#define GEMM_SMEM (NSTG*STG)

__global__ __launch_bounds__(256, 2) void mma_gemm(const float* __restrict__ bias,
                                                   float* __restrict__ outp,
                                                   int K, int Nn, int epi)
{
    extern __shared__ char smem[];
    uint32_t sb = smem_u32(smem);

    const __half *Ah, *Bw;
    if (epi == 0) { Ah = g_cat; Bw = g_w1; }
    else          { Ah = g_hid; Bw = g_w2; }

    int tid = threadIdx.x, lane = tid & 31, wid = tid >> 5;
    int warpM = wid & 1, warpN = wid >> 1;
    int bm = blockIdx.y*128, bn = blockIdx.x*128;
    int nch = K >> 6;                      // 64 floats per chunk

    const __half* Abase = Ah + (size_t)bm*K;
    const __half* Bbase = Bw + (size_t)bn*K;

    float acc[4][4][4];
#pragma unroll
    for (int a = 0; a < 4; a++)
#pragma unroll
        for (int b = 0; b < 4; b++)
#pragma unroll
            for (int c = 0; c < 4; c++) acc[a][b][c] = 0.f;

    // ---- async chunk loader (8x cp.async 16B per thread) ----
#define LOAD_CHUNK(i) do { \
    int _k0 = (i) << 6; \
    uint32_t _st = sb + ((i) % NSTG) * STG; \
    _Pragma("unroll") \
    for (int _j = 0; _j < 4; _j++) { \
        int _u = tid + _j*256; \
        int _r = _u >> 3, _kb = _u & 7; \
        size_t _go = (size_t)_r*K + _k0 + _kb*8; \
        uint32_t _do_ = (uint32_t)(_r*144 + _kb*16); \
        CP16(_st + _do_,          Abase + _go); \
        CP16(_st + 18432 + _do_,  Bbase + _go); \
    } \
} while (0)

    // prologue: 2 chunks in flight
    LOAD_CHUNK(0); CP_COMMIT();
    if (nch > 1) LOAD_CHUNK(1);
    CP_COMMIT();

    // ldmatrix address components
    int arow = warpM*64 + (lane & 7) + ((lane >> 3) & 1)*8;   // + mf*16
    uint32_t akb = ((lane >> 4) & 1)*16;                      // + kstep*32
    int brow = warpN*32 + ((lane >> 4) & 1)*8 + (lane & 7);   // + npair*16
    uint32_t bkb = ((lane >> 3) & 1)*16;

    for (int i = 0; i < nch; i++) {
        CP_WAIT1();
        __syncthreads();
        if (i + 2 < nch) LOAD_CHUNK(i + 2);
        CP_COMMIT();

        uint32_t st = sb + (i % NSTG)*STG;
#pragma unroll
        for (int ks = 0; ks < 4; ks++) {
            uint32_t kB = ks*32;
            uint32_t a4[4][4], bfr[2][4];
#pragma unroll
            for (int mf = 0; mf < 4; mf++)
                ldsm4(a4[mf], st + (uint32_t)(arow + mf*16)*144 + akb + kB);
#pragma unroll
            for (int np = 0; np < 2; np++)
                ldsm4(bfr[np], st + 18432 + (uint32_t)(brow + np*16)*144 + bkb + kB);
#pragma unroll
            for (int mf = 0; mf < 4; mf++)
#pragma unroll
                for (int nf = 0; nf < 4; nf++) {
                    const uint32_t* bp = &bfr[nf >> 1][(nf & 1)*2];
                    mma16816(acc[mf][nf], a4[mf], bp);
                }
        }
    }

    // ---- epilogue ----
    int r0 = bm + warpM*64 + (lane >> 2);
    int cbase = bn + warpN*32 + (lane & 3)*2;
#pragma unroll
    for (int mf = 0; mf < 4; mf++) {
        int row0 = r0 + mf*16;
        int row1 = row0 + 8;
#pragma unroll
        for (int nf = 0; nf < 4; nf++) {
            int col = cbase + nf*8;
            float b0 = bias[col], b1 = bias[col + 1];
            float v00 = acc[mf][nf][0] + b0;
            float v01 = acc[mf][nf][1] + b1;
            float v10 = acc[mf][nf][2] + b0;
            float v11 = acc[mf][nf][3] + b1;
            if (epi == 0) {
                v00 = 0.5f*v00*(1.f + erff(v00*0.70710678118654752f));
                v01 = 0.5f*v01*(1.f + erff(v01*0.70710678118654752f));
                v10 = 0.5f*v10*(1.f + erff(v10*0.70710678118654752f));
                v11 = 0.5f*v11*(1.f + erff(v11*0.70710678118654752f));
                *(__half2*)(g_hid + (size_t)row0*HIDD + col) =
                    __half2(__float2half_rn(v00), __float2half_rn(v01));
                *(__half2*)(g_hid + (size_t)row1*HIDD + col) =
                    __half2(__float2half_rn(v10), __float2half_rn(v11));
            } else {
                int bb0 = row0 >> 14, n0 = row0 & 16383;
                int bb1 = row1 >> 14, n1 = row1 & 16383;
                size_t ob0 = (((size_t)bb0*2*Ntok) + Ntok + n0)*256;
                size_t ob1 = (((size_t)bb1*2*Ntok) + Ntok + n1)*256;
                *(float2*)(outp + ob0 + col) = make_float2(v00, v01);
                *(float2*)(outp + ob1 + col) = make_float2(v10, v11);
            }
        }
    }
}

// ---------------- launch -------------------------------------------
extern "C" void kernel_launch(void* const* d_in, const int* in_sizes, int n_in,
                              void* d_out, int out_size)
{
    (void)in_sizes; (void)n_in; (void)out_size;
    const float* x      = (const float*)d_in[0];
    const float* loc    = (const float*)d_in[1];
    const float* src    = (const float*)d_in[2];
    const float* w_delta = (const float*)d_in[7];
    const float* b_delta = (const float*)d_in[8];
    const float* n1g    = (const float*)d_in[9];
    const float* n1b    = (const float*)d_in[10];
    const float* conv_w = (const float*)d_in[11];
    const float* conv_b = (const float*)d_in[12];
    const float* n2g    = (const float*)d_in[13];
    const float* n2b    = (const float*)d_in[14];
    const float* fc1w   = (const float*)d_in[15];
    const float* fc1b   = (const float*)d_in[16];
    const float* fc2w   = (const float*)d_in[17];
    const float* fc2b   = (const float*)d_in[18];
    float* out = (float*)d_out;
    float* out_loc = out + (size_t)Bsz*2*Ntok*Dm;

    cudaFuncSetAttribute(mma_gemm, cudaFuncAttributeMaxDynamicSharedMemorySize, GEMM_SMEM);

    // weight transpose + fp16 (independent of data path)
    k_wsplit<<<dim3(HIDD/32, CATD/32), dim3(32,8)>>>(fc1w, CATD, HIDD, 0);
    k_wsplit<<<dim3(Dm/32,  HIDD/32), dim3(32,8)>>>(fc2w, HIDD, Dm, 1);

    // zero scatter accumulator
    {
        size_t n4 = (size_t)Bsz*HWm*257/4;
        k_zero_acc<<<(unsigned)((n4 + 255)/256), 256>>>();
    }
    k_delta<<<Bsz*Ntok/8, 256>>>(x, loc, w_delta, b_delta, n1g, n1b, out_loc);
    {
        size_t n4 = (size_t)Bsz*Ntok*Dm/4;
        k_copyx<<<(unsigned)((n4 + 255)/256), 256>>>((const float4*)x, (float4*)out);
    }
    k_scatter<<<Bsz*Ntok/8, 256>>>(x, loc);
    k_recon<<<Bsz*HWm/8, 256>>>();
    k_patch<<<Bsz*Ntok/8, 512>>>(src, conv_w, conv_b, n2g, n2b);
    k_gather<<<Bsz*Ntok/8, 256>>>();

    // MLP on tensor cores (fp16 single-term, fp32 accumulate)
    mma_gemm<<<dim3(HIDD/128, Mrows/128), 256, GEMM_SMEM>>>(fc1b, nullptr, CATD, HIDD, 0);
    mma_gemm<<<dim3(Dm/128,   Mrows/128), 256, GEMM_SMEM>>>(fc2b, out,     HIDD, Dm,   1);
}

// round 7
// speedup vs baseline: 4.6591x; 1.0596x over previous
#include <cuda_runtime.h>
#include <cuda_fp16.h>
#include <math.h>
#include <stdint.h>

// ---------------- problem constants (fixed shapes) ----------------
#define Bsz   4
#define Ntok  16384
#define Dm    256
#define LDm   64
#define Hm    128
#define Wm    128
#define HWm   (Hm*Wm)
#define Hsrc  512
#define Wsrc  512
#define CATD  320
#define HIDD  1024
#define Mrows (Bsz*Ntok)

// ---------------- scratch (static device globals; no allocs) ------
__device__ __align__(16) float g_loc_extra[Bsz*Ntok*2];
__device__ __align__(16) float g_acc [Bsz*HWm*257];
__device__ __align__(16) __half g_fmap[(size_t)Bsz*HWm*256];
__device__ __align__(16) __half g_cat[(size_t)Mrows*CATD];
__device__ __align__(16) __half g_hid[(size_t)Mrows*HIDD];
__device__ __align__(16) __half g_w1[(size_t)HIDD*CATD];     // fc1_w^T fp16 [N][K]
__device__ __align__(16) __half g_w2[(size_t)Dm*HIDD];       // fc2_w^T fp16 [N][K]

// ================= PTX helpers (base sm_80+ features only) ==========
__device__ __forceinline__ uint32_t smem_u32(const void* p) {
    uint32_t a;
    asm("{ .reg .u64 t; cvta.to.shared.u64 t, %1; cvt.u32.u64 %0, t; }" : "=r"(a) : "l"(p));
    return a;
}
#define CP16(smem, gptr) \
    asm volatile("cp.async.cg.shared.global [%0], [%1], 16;" :: "r"(smem), "l"(gptr) : "memory")
#define CP_COMMIT() asm volatile("cp.async.commit_group;" ::: "memory")
#define CP_WAIT1()  asm volatile("cp.async.wait_group 1;" ::: "memory")

__device__ __forceinline__ void ldsm4(uint32_t* r, uint32_t addr) {
    asm volatile("ldmatrix.sync.aligned.m8n8.x4.shared.b16 {%0,%1,%2,%3}, [%4];"
        : "=r"(r[0]), "=r"(r[1]), "=r"(r[2]), "=r"(r[3]) : "r"(addr));
}
__device__ __forceinline__ void mma16816(float* d, const uint32_t* a, const uint32_t* b) {
    asm volatile("mma.sync.aligned.m16n8k16.row.col.f32.f16.f16.f32 "
        "{%0,%1,%2,%3}, {%4,%5,%6,%7}, {%8,%9}, {%0,%1,%2,%3};"
        : "+f"(d[0]), "+f"(d[1]), "+f"(d[2]), "+f"(d[3])
        : "r"(a[0]), "r"(a[1]), "r"(a[2]), "r"(a[3]), "r"(b[0]), "r"(b[1]));
}

// ---------------- K0: zero the scatter accumulator ----------------
__global__ void k_zero_acc() {
    size_t n4 = (size_t)Bsz*HWm*257/4;
    size_t i = (size_t)blockIdx.x*blockDim.x + threadIdx.x;
    if (i < n4) ((float4*)g_acc)[i] = make_float4(0.f,0.f,0.f,0.f);
}

// ---------------- K1: LN1 + delta + loc_extra + loc outputs -------
__global__ void k_delta(const float* __restrict__ x, const float* __restrict__ loc,
                        const float* __restrict__ wd, const float* __restrict__ bd,
                        const float* __restrict__ n1g, const float* __restrict__ n1b,
                        float* __restrict__ out_loc_base)
{
    int w = (blockIdx.x*blockDim.x + threadIdx.x) >> 5;
    int lane = threadIdx.x & 31;
    if (w >= Bsz*Ntok) return;
    const float* xr = x + (size_t)w*Dm;
    float v[8], s = 0.f, sq = 0.f;
#pragma unroll
    for (int k = 0; k < 8; k++) { v[k] = xr[lane + 32*k]; s += v[k]; sq += v[k]*v[k]; }
#pragma unroll
    for (int o = 16; o > 0; o >>= 1) { s += __shfl_xor_sync(0xffffffffu, s, o); sq += __shfl_xor_sync(0xffffffffu, sq, o); }
    float m   = s  * (1.f/256.f);
    float var = sq * (1.f/256.f) - m*m;
    float r   = rsqrtf(var + 1e-5f);
    float d0 = 0.f, d1 = 0.f;
#pragma unroll
    for (int k = 0; k < 8; k++) {
        int c = lane + 32*k;
        float y = (v[k]-m)*r*n1g[c] + n1b[c];
        d0 += y * wd[2*c];
        d1 += y * wd[2*c+1];
    }
#pragma unroll
    for (int o = 16; o > 0; o >>= 1) { d0 += __shfl_xor_sync(0xffffffffu, d0, o); d1 += __shfl_xor_sync(0xffffffffu, d1, o); }
    if (lane == 0) {
        float l0 = loc[2*w], l1 = loc[2*w+1];
        float e0 = fminf(fmaxf(l0 + (d0 + bd[0])*0.01f, 0.f), 1.f);
        float e1 = fminf(fmaxf(l1 + (d1 + bd[1])*0.01f, 0.f), 1.f);
        g_loc_extra[2*w]   = e0;
        g_loc_extra[2*w+1] = e1;
        int b = w / Ntok, n = w % Ntok;
        float* o1 = out_loc_base + ((size_t)b*2*Ntok + n)*2;
        o1[0] = l0; o1[1] = l1;
        float* o2 = out_loc_base + ((size_t)b*2*Ntok + Ntok + n)*2;
        o2[0] = e0; o2[1] = e1;
    }
}

// ---------------- K2: copy x into first-half tokens of output -----
__global__ void k_copyx(const float4* __restrict__ x, float4* __restrict__ out)
{
    size_t per = (size_t)Ntok*Dm/4;
    size_t i = (size_t)blockIdx.x*blockDim.x + threadIdx.x;
    if (i >= (size_t)Bsz*per) return;
    size_t b = i / per, rem = i % per;
    out[b*2*per + rem] = x[i];
}

// ---------------- K3: token2map scatter-add -----------------------
__global__ void k_scatter(const float* __restrict__ x, const float* __restrict__ loc)
{
    int w = (blockIdx.x*blockDim.x + threadIdx.x) >> 5;
    int lane = threadIdx.x & 31;
    if (w >= Bsz*Ntok) return;
    int b = w / Ntok;
    float lx = fminf(fmaxf(loc[2*w],   0.f), 1.f) * (float)(Wm-1);
    float ly = fminf(fmaxf(loc[2*w+1], 0.f), 1.f) * (float)(Hm-1);
    int xi = (int)rintf(lx);
    int yi = (int)rintf(ly);
    size_t base = ((size_t)b*HWm + yi*Wm + xi) * 257;
    const float* xr = x + (size_t)w*Dm;
    for (int c = lane; c < 257; c += 32) {
        float val = (c < 256) ? xr[c] : 1.f;
        atomicAdd(&g_acc[base + c], val);
    }
}

// ---------------- K5: fused normalize + gaussian 3x3 + reconstruct
// One block handles a 4-row x 8-col pixel tile; thread = channel.
__global__ void k_recon()
{
    int tile = blockIdx.x;                 // 0 .. B*HW/32-1 (2048)
    int b    = tile >> 9;                  // 512 tiles per batch
    int rem  = tile & 511;
    int y0   = (rem >> 4) << 2;            // 32 y-tiles of 4 rows
    int x0   = (rem & 15) << 3;            // 16 x-tiles of 8 cols
    int c    = threadIdx.x;                // 0..255 = channel

    __shared__ float s_inv[6][10];
    __shared__ float s_msk[6][10];

    if (c < 60) {
        int r = c / 10, cc = c % 10;
        int ny = y0 - 1 + r, nx = x0 - 1 + cc;
        bool valid = (ny >= 0 && ny < Hm && nx >= 0 && nx < Wm);
        float cnt = valid ? g_acc[((size_t)b*HWm + ny*Wm + nx)*257 + 256] : 0.f;
        float msk = (valid && cnt > 0.f) ? 1.f : 0.f;
        s_msk[r][cc] = msk;
        s_inv[r][cc] = valid ? (msk / (cnt + 1e-6f)) : 0.f;
    }
    __syncthreads();

    float e1 = expf(-0.125f), e2 = expf(-0.25f);
    float wsum = 1.f + 4.f*e1 + 4.f*e2;
    float w0 = 1.f/wsum, w1 = e1/wsum, w2 = e2/wsum;
    float wgt[3] = {w0, w1, w2};           // by |dy|+|dx| pattern below

    float vals[3][10];
    // load row r (0..5 relative) into slot
#define LOAD_ROW(r, slot) do { \
    int _ny = y0 - 1 + (r); \
    bool _rok = (_ny >= 0 && _ny < Hm); \
    _Pragma("unroll") \
    for (int _cc = 0; _cc < 10; _cc++) { \
        int _nx = x0 - 1 + _cc; \
        bool _ok = _rok && (_nx >= 0 && _nx < Wm); \
        float _v = _ok ? g_acc[((size_t)b*HWm + _ny*Wm + _nx)*257 + c] : 0.f; \
        vals[slot][_cc] = _v * s_inv[r][_cc]; \
    } \
} while (0)

    LOAD_ROW(0, 0);
    LOAD_ROW(1, 1);

#pragma unroll
    for (int yi = 0; yi < 4; yi++) {
        LOAD_ROW(yi + 2, (yi + 2) % 3);
        float* vm = vals[yi % 3];
        float* v0 = vals[(yi + 1) % 3];
        float* vp = vals[(yi + 2) % 3];
        const float* mm = s_msk[yi];
        const float* m0 = s_msk[yi + 1];
        const float* mp = s_msk[yi + 2];
#pragma unroll
        for (int i = 0; i < 8; i++) {
            float feature = v0[i + 1];
            float mask_c  = m0[i + 1];
            float filt  = wgt[0]*v0[i+1]
                        + wgt[1]*(v0[i] + v0[i+2] + vm[i+1] + vp[i+1])
                        + wgt[2]*(vm[i] + vm[i+2] + vp[i] + vp[i+2]);
            float filtm = wgt[0]*m0[i+1]
                        + wgt[1]*(m0[i] + m0[i+2] + mm[i+1] + mp[i+1])
                        + wgt[2]*(mm[i] + mm[i+2] + mp[i] + mp[i+2]);
            float f_i = filt / (filtm + 1e-6f);
            f_i = (filtm > 0.f) ? f_i : 0.f;
            float outv = feature + (1.f - mask_c)*f_i;
            g_fmap[((size_t)b*HWm + (y0 + yi)*Wm + x0 + i)*256 + c] = __float2half_rn(outv);
        }
    }
#undef LOAD_ROW
}

// ---------------- K6: patch sample + conv + LN2 (8 tokens/block) --
__device__ __forceinline__ float srctap(const float* sp, int xi, int yi, float w)
{
    if (xi < 0 || xi >= Wsrc || yi < 0 || yi >= Hsrc) return 0.f;
    return w * sp[yi*Wsrc + xi];
}

__global__ __launch_bounds__(512) void k_patch(const float* __restrict__ src,
                        const float* __restrict__ cw,
                        const float* __restrict__ cb,  const float* __restrict__ n2g,
                        const float* __restrict__ n2b)
{
    __shared__ float s_cw[64*49];          // padded stride 49 (conflict-free)
    __shared__ float s_patch[8][48];
    __shared__ float s_red[8][4];

    int tid = threadIdx.x;
    for (int i = tid; i < 64*48; i += 512)
        s_cw[(i/48)*49 + (i%48)] = cw[i];

    int sub = tid >> 6;                    // 0..7 token slot
    int t   = tid & 63;
    int tok = blockIdx.x*8 + sub;
    int b   = tok >> 14;

    float lx = g_loc_extra[2*tok], ly = g_loc_extra[2*tok+1];
    if (t < 48) {
        int cch = t >> 4, r = (t >> 2) & 3, col = t & 3;
        float gx = (lx + ((float)col - 1.5f)*(1.f/511.f)) * 512.f - 0.5f;
        float gy = (ly + ((float)r   - 1.5f)*(1.f/511.f)) * 512.f - 0.5f;
        float x0f = floorf(gx), y0f = floorf(gy);
        float wx = gx - x0f, wy = gy - y0f;
        int x0 = (int)x0f, y0 = (int)y0f;
        const float* sp = src + ((size_t)b*3 + cch)*Hsrc*Wsrc;
        float v = srctap(sp, x0,   y0,   (1.f-wx)*(1.f-wy))
                + srctap(sp, x0+1, y0,   wx*(1.f-wy))
                + srctap(sp, x0,   y0+1, (1.f-wx)*wy)
                + srctap(sp, x0+1, y0+1, wx*wy);
        s_patch[sub][t] = v;
    }
    __syncthreads();

    float acc = cb[t];
#pragma unroll
    for (int k = 0; k < 48; k++) acc += s_patch[sub][k] * s_cw[t*49 + k];

    float s = acc, sq = acc*acc;
#pragma unroll
    for (int o = 16; o > 0; o >>= 1) { s += __shfl_xor_sync(0xffffffffu, s, o); sq += __shfl_xor_sync(0xffffffffu, sq, o); }
    int wh = t >> 5;
    if ((t & 31) == 0) { s_red[sub][wh] = s; s_red[sub][2 + wh] = sq; }
    __syncthreads();
    s  = s_red[sub][0] + s_red[sub][1];
    sq = s_red[sub][2] + s_red[sub][3];
    float m   = s  * (1.f/64.f);
    float var = sq * (1.f/64.f) - m*m;
    float rr  = rsqrtf(var + 1e-5f);
    float v = (acc - m)*rr*n2g[t] + n2b[t];
    g_cat[(size_t)tok*CATD + 256 + t] = __float2half_rn(v);
}

// ---------------- K7: bilinear gather from fmap (fp16) -> cat -----
__global__ void k_gather()
{
    int tok = (blockIdx.x*blockDim.x + threadIdx.x) >> 5;
    int lane = threadIdx.x & 31;
    if (tok >= Bsz*Ntok) return;
    int b = tok >> 14;
    float gx = g_loc_extra[2*tok]   * 128.f - 0.5f;
    float gy = g_loc_extra[2*tok+1] * 128.f - 0.5f;
    float x0f = floorf(gx), y0f = floorf(gy);
    float wx = gx - x0f, wy = gy - y0f;
    int x0 = (int)x0f, y0 = (int)y0f;
    int x1 = x0 + 1,   y1 = y0 + 1;
    float vx0 = (x0 >= 0 && x0 < Wm) ? 1.f : 0.f;
    float vx1 = (x1 >= 0 && x1 < Wm) ? 1.f : 0.f;
    float vy0 = (y0 >= 0 && y0 < Hm) ? 1.f : 0.f;
    float vy1 = (y1 >= 0 && y1 < Hm) ? 1.f : 0.f;
    float w00 = (1.f-wx)*(1.f-wy)*vx0*vy0;
    float w10 = wx*(1.f-wy)*vx1*vy0;
    float w01 = (1.f-wx)*wy*vx0*vy1;
    float w11 = wx*wy*vx1*vy1;
    int cx0 = min(max(x0,0),Wm-1), cx1 = min(max(x1,0),Wm-1);
    int cy0 = min(max(y0,0),Hm-1), cy1 = min(max(y1,0),Hm-1);
    const __half* base = g_fmap + (size_t)b*HWm*256;
    const __half2* p00 = (const __half2*)(base + (size_t)(cy0*Wm + cx0)*256);
    const __half2* p10 = (const __half2*)(base + (size_t)(cy0*Wm + cx1)*256);
    const __half2* p01 = (const __half2*)(base + (size_t)(cy1*Wm + cx0)*256);
    const __half2* p11 = (const __half2*)(base + (size_t)(cy1*Wm + cx1)*256);
    __half2* outp = (__half2*)(g_cat + (size_t)tok*CATD);
#pragma unroll
    for (int k = 0; k < 4; k++) {
        int p = lane + 32*k;               // pair index 0..127
        float2 a = __half22float2(p00[p]);
        float2 d = __half22float2(p10[p]);
        float2 e = __half22float2(p01[p]);
        float2 f = __half22float2(p11[p]);
        float r0 = w00*a.x + w10*d.x + w01*e.x + w11*f.x;
        float r1 = w00*a.y + w10*d.y + w01*e.y + w11*f.y;
        outp[p] = __floats2half2_rn(r0, r1);
    }
}

// ---------------- weight transpose + fp16: [K][N] -> [N][K] -------
__global__ void k_wsplit(const float* __restrict__ in, int K, int N, int which)
{
    __half* oh = which ? g_w2 : g_w1;
    __shared__ float t[32][33];
    int k0 = blockIdx.y*32, n0 = blockIdx.x*32;
    int x = threadIdx.x, y = threadIdx.y;
#pragma unroll
    for (int i = 0; i < 32; i += 8)
        t[y+i][x] = in[(size_t)(k0+y+i)*N + n0 + x];
    __syncthreads();
#pragma unroll
    for (int i = 0; i < 32; i += 8)
        oh[(size_t)(n0+y+i)*K + k0 + x] = __float2half_rn(t[x][y+i]);
}

// ---------------- HMMA fp16 GEMM (128x128 CTA, K-chunk 64) --------
#define STG   36864
#define NSTG  3
#define GEMM_SMEM (NSTG*STG)

__global__ __launch_bounds__(256, 2) void mma_gemm(const float* __restrict__ bias,
                                                   float* __restrict__ outp,
                                                   int K, int Nn, int epi)
{
    extern __shared__ char smem[];
    uint32_t sb = smem_u32(smem);

    const __half *Ah, *Bw;
    if (epi == 0) { Ah = g_cat; Bw = g_w1; }
    else          { Ah = g_hid; Bw = g_w2; }

    int tid = threadIdx.x, lane = tid & 31, wid = tid >> 5;
    int warpM = wid & 1, warpN = wid >> 1;
    int bm = blockIdx.y*128, bn = blockIdx.x*128;
    int nch = K >> 6;                      // 64 halves per chunk

    const __half* Abase = Ah + (size_t)bm*K;
    const __half* Bbase = Bw + (size_t)bn*K;

    float acc[4][4][4];
#pragma unroll
    for (int a = 0; a < 4; a++)
#pragma unroll
        for (int b = 0; b < 4; b++)
#pragma unroll
            for (int c = 0; c < 4; c++) acc[a][b][c] = 0.f;

#define LOAD_CHUNK(i) do { \
    int _k0 = (i) << 6; \
    uint32_t _st = sb + ((i) % NSTG) * STG; \
    _Pragma("unroll") \
    for (int _j = 0; _j < 4; _j++) { \
        int _u = tid + _j*256; \
        int _r = _u >> 3, _kb = _u & 7; \
        size_t _go = (size_t)_r*K + _k0 + _kb*8; \
        uint32_t _do_ = (uint32_t)(_r*144 + _kb*16); \
        CP16(_st + _do_,          Abase + _go); \
        CP16(_st + 18432 + _do_,  Bbase + _go); \
    } \
} while (0)

    LOAD_CHUNK(0); CP_COMMIT();
    if (nch > 1) LOAD_CHUNK(1);
    CP_COMMIT();

    int arow = warpM*64 + (lane & 7) + ((lane >> 3) & 1)*8;
    uint32_t akb = ((lane >> 4) & 1)*16;
    int brow = warpN*32 + ((lane >> 4) & 1)*8 + (lane & 7);
    uint32_t bkb = ((lane >> 3) & 1)*16;

    for (int i = 0; i < nch; i++) {
        CP_WAIT1();
        __syncthreads();
        if (i + 2 < nch) LOAD_CHUNK(i + 2);
        CP_COMMIT();

        uint32_t st = sb + (i % NSTG)*STG;
#pragma unroll
        for (int ks = 0; ks < 4; ks++) {
            uint32_t kB = ks*32;
            uint32_t a4[4][4], bfr[2][4];
#pragma unroll
            for (int mf = 0; mf < 4; mf++)
                ldsm4(a4[mf], st + (uint32_t)(arow + mf*16)*144 + akb + kB);
#pragma unroll
            for (int np = 0; np < 2; np++)
                ldsm4(bfr[np], st + 18432 + (uint32_t)(brow + np*16)*144 + bkb + kB);
#pragma unroll
            for (int mf = 0; mf < 4; mf++)
#pragma unroll
                for (int nf = 0; nf < 4; nf++) {
                    const uint32_t* bp = &bfr[nf >> 1][(nf & 1)*2];
                    mma16816(acc[mf][nf], a4[mf], bp);
                }
        }
    }

    // ---- epilogue ----
    int r0 = bm + warpM*64 + (lane >> 2);
    int cbase = bn + warpN*32 + (lane & 3)*2;
#pragma unroll
    for (int mf = 0; mf < 4; mf++) {
        int row0 = r0 + mf*16;
        int row1 = row0 + 8;
#pragma unroll
        for (int nf = 0; nf < 4; nf++) {
            int col = cbase + nf*8;
            float b0 = bias[col], b1 = bias[col + 1];
            float v00 = acc[mf][nf][0] + b0;
            float v01 = acc[mf][nf][1] + b1;
            float v10 = acc[mf][nf][2] + b0;
            float v11 = acc[mf][nf][3] + b1;
            if (epi == 0) {
                v00 = 0.5f*v00*(1.f + erff(v00*0.70710678118654752f));
                v01 = 0.5f*v01*(1.f + erff(v01*0.70710678118654752f));
                v10 = 0.5f*v10*(1.f + erff(v10*0.70710678118654752f));
                v11 = 0.5f*v11*(1.f + erff(v11*0.70710678118654752f));
                *(__half2*)(g_hid + (size_t)row0*HIDD + col) =
                    __half2(__float2half_rn(v00), __float2half_rn(v01));
                *(__half2*)(g_hid + (size_t)row1*HIDD + col) =
                    __half2(__float2half_rn(v10), __float2half_rn(v11));
            } else {
                int bb0 = row0 >> 14, n0 = row0 & 16383;
                int bb1 = row1 >> 14, n1 = row1 & 16383;
                size_t ob0 = (((size_t)bb0*2*Ntok) + Ntok + n0)*256;
                size_t ob1 = (((size_t)bb1*2*Ntok) + Ntok + n1)*256;
                *(float2*)(outp + ob0 + col) = make_float2(v00, v01);
                *(float2*)(outp + ob1 + col) = make_float2(v10, v11);
            }
        }
    }
}

// ---------------- launch -------------------------------------------
extern "C" void kernel_launch(void* const* d_in, const int* in_sizes, int n_in,
                              void* d_out, int out_size)
{
    (void)in_sizes; (void)n_in; (void)out_size;
    const float* x      = (const float*)d_in[0];
    const float* loc    = (const float*)d_in[1];
    const float* src    = (const float*)d_in[2];
    const float* w_delta = (const float*)d_in[7];
    const float* b_delta = (const float*)d_in[8];
    const float* n1g    = (const float*)d_in[9];
    const float* n1b    = (const float*)d_in[10];
    const float* conv_w = (const float*)d_in[11];
    const float* conv_b = (const float*)d_in[12];
    const float* n2g    = (const float*)d_in[13];
    const float* n2b    = (const float*)d_in[14];
    const float* fc1w   = (const float*)d_in[15];
    const float* fc1b   = (const float*)d_in[16];
    const float* fc2w   = (const float*)d_in[17];
    const float* fc2b   = (const float*)d_in[18];
    float* out = (float*)d_out;
    float* out_loc = out + (size_t)Bsz*2*Ntok*Dm;

    cudaFuncSetAttribute(mma_gemm, cudaFuncAttributeMaxDynamicSharedMemorySize, GEMM_SMEM);

    // weight transpose + fp16 (independent of data path)
    k_wsplit<<<dim3(HIDD/32, CATD/32), dim3(32,8)>>>(fc1w, CATD, HIDD, 0);
    k_wsplit<<<dim3(Dm/32,  HIDD/32), dim3(32,8)>>>(fc2w, HIDD, Dm, 1);

    // zero scatter accumulator
    {
        size_t n4 = (size_t)Bsz*HWm*257/4;
        k_zero_acc<<<(unsigned)((n4 + 255)/256), 256>>>();
    }
    k_delta<<<Bsz*Ntok/8, 256>>>(x, loc, w_delta, b_delta, n1g, n1b, out_loc);
    {
        size_t n4 = (size_t)Bsz*Ntok*Dm/4;
        k_copyx<<<(unsigned)((n4 + 255)/256), 256>>>((const float4*)x, (float4*)out);
    }
    k_scatter<<<Bsz*Ntok/8, 256>>>(x, loc);
    k_recon<<<Bsz*HWm/32, 256>>>();
    k_patch<<<Bsz*Ntok/8, 512>>>(src, conv_w, conv_b, n2g, n2b);
    k_gather<<<Bsz*Ntok/8, 256>>>();

    // MLP on tensor cores (fp16 single-term, fp32 accumulate)
    mma_gemm<<<dim3(HIDD/128, Mrows/128), 256, GEMM_SMEM>>>(fc1b, nullptr, CATD, HIDD, 0);
    mma_gemm<<<dim3(Dm/128,   Mrows/128), 256, GEMM_SMEM>>>(fc2b, out,     HIDD, Dm,   1);
}